// round 3
// baseline (speedup 1.0000x reference)
#include <cuda_runtime.h>
#include <cuda_bf16.h>
#include <math.h>

#define BATCH 64
#define SEQ   1024
#define DIM   200
#define NCLS  31
#define NHEAD 8
#define LN_EPS 1e-5f
#define ND2   (DIM/2)     /* 100 float2 columns */
#define WPAD  102         /* padded float2 row stride for W smem */
#define SBM   128         /* scores tile */
#define KT_STRIDE 130     /* padded transposed-K smem stride (floats) */

// ---------------- scratch (static device memory; no allocations) ----------------
static __device__ float g_h[BATCH * SEQ * DIM];     // 52.4 MB
static __device__ float g_p[BATCH * SEQ * DIM];     // 52.4 MB
static __device__ float g_c[BATCH * SEQ * DIM];     // 52.4 MB
static __device__ float g_A[(size_t)BATCH * SEQ * SEQ]; // 268 MB attention matrix
static __device__ float g_We[DIM * DIM];            // collapsed Wm (sum of 8 head blocks)
static __device__ float g_stats[2 * BATCH];         // per-batch mean, rstd

// ---------------- f32x2 packed-FMA helpers (Blackwell FFMA2) ----------------
__device__ __forceinline__ unsigned long long pack2(float x) {
    unsigned long long r;
    asm("mov.b64 %0, {%1, %1};" : "=l"(r) : "f"(x));
    return r;
}
__device__ __forceinline__ unsigned long long ffma2(unsigned long long a,
                                                    unsigned long long b,
                                                    unsigned long long c) {
    unsigned long long d;
    asm("fma.rn.f32x2 %0, %1, %2, %3;" : "=l"(d) : "l"(a), "l"(b), "l"(c));
    return d;
}
__device__ __forceinline__ float2 unpack2(unsigned long long v) {
    float2 f;
    asm("mov.b64 {%0, %1}, %2;" : "=f"(f.x), "=f"(f.y) : "l"(v));
    return f;
}

// ---------------- small kernels ----------------
__global__ void wmeff_kernel(const float* __restrict__ Wm, float* __restrict__ We) {
    int i = blockIdx.x * blockDim.x + threadIdx.x;
    if (i >= DIM * DIM) return;
    int row = i / DIM, col = i % DIM;
    float s = 0.f;
#pragma unroll
    for (int h = 0; h < NHEAD; h++) s += Wm[(h * DIM + row) * DIM + col];
    We[i] = s;
}

__global__ void embed_kernel(const int* __restrict__ x, const float4* __restrict__ emb,
                             const float4* __restrict__ pos, float4* __restrict__ h) {
    int g = blockIdx.x * blockDim.x + threadIdx.x;
    const int Q = DIM / 4; // 50
    if (g >= BATCH * SEQ * Q) return;
    int q = g % Q;
    int r = g / Q;
    int s = r % SEQ;
    int tok = x[r];
    float4 e = emb[(size_t)tok * Q + q];
    float4 p = pos[(size_t)s * Q + q];
    h[g] = make_float4(e.x + p.x, e.y + p.y, e.z + p.z, e.w + p.w);
}

// ---------------- generic N=200 GEMM:  Y = op(X @ W + bias (+res)) ----------------
// 200 threads, BM=64 rows, full N=200, K tiled by BK (K % BK == 0).
// Per thread: 8 rows (ty+8i) x 8 cols as 4 float2 (float2-col = tx+25j). f32x2 FMAs.
template <int BK, bool RELU, bool ADDRES>
__global__ void __launch_bounds__(200) gemm200_kernel(
    const float* __restrict__ X, long long xStride,
    const float* __restrict__ W, long long wStride,
    const float* __restrict__ bias,
    const float* __restrict__ res,
    float* __restrict__ Y, long long yStride,
    int K)
{
    extern __shared__ char smem_raw[];
    float*  As = (float*)smem_raw;                                  // [64][BK]
    float2* Ws = (float2*)(smem_raw + 64 * BK * sizeof(float));     // [BK][WPAD]

    const int b = blockIdx.y;
    const long long row0 = (long long)blockIdx.x * 64;
    const float* Xb = X + (long long)b * xStride + row0 * K;
    const float* Wb = W + (long long)b * wStride;

    const int tid = threadIdx.x;
    const int tx = tid % 25;
    const int ty = tid / 25;

    unsigned long long acc[8][4];
#pragma unroll
    for (int i = 0; i < 8; i++)
#pragma unroll
        for (int j = 0; j < 4; j++) acc[i][j] = 0ULL;

    for (int k0 = 0; k0 < K; k0 += BK) {
        // stage A tile (coalesced: consecutive threads -> consecutive k)
        for (int i = tid; i < 64 * BK; i += 200) {
            int r = i / BK, c = i % BK;
            As[i] = Xb[(long long)r * K + k0 + c];
        }
        // stage W tile as float2 rows
        for (int i = tid; i < BK * ND2; i += 200) {
            int kk = i / ND2, n2 = i % ND2;
            Ws[kk * WPAD + n2] = ((const float2*)(Wb + (long long)(k0 + kk) * DIM))[n2];
        }
        __syncthreads();
#pragma unroll 2
        for (int k = 0; k < BK; k++) {
            unsigned long long a2[8];
#pragma unroll
            for (int i = 0; i < 8; i++) a2[i] = pack2(As[(ty + 8 * i) * BK + k]);
            unsigned long long w[4];
#pragma unroll
            for (int j = 0; j < 4; j++)
                w[j] = *(const unsigned long long*)&Ws[k * WPAD + tx + 25 * j];
#pragma unroll
            for (int i = 0; i < 8; i++)
#pragma unroll
                for (int j = 0; j < 4; j++) acc[i][j] = ffma2(a2[i], w[j], acc[i][j]);
        }
        __syncthreads();
    }

    float2 bb[4];
#pragma unroll
    for (int j = 0; j < 4; j++)
        bb[j] = bias ? ((const float2*)bias)[tx + 25 * j] : make_float2(0.f, 0.f);

#pragma unroll
    for (int i = 0; i < 8; i++) {
        size_t grow = (size_t)b * yStride + (size_t)(row0 + ty + 8 * i) * DIM;
        float2* yrow = (float2*)(Y + grow);
        const float2* rrow = ADDRES ? (const float2*)(res + grow) : (const float2*)0;
#pragma unroll
        for (int j = 0; j < 4; j++) {
            float2 v = unpack2(acc[i][j]);
            v.x += bb[j].x; v.y += bb[j].y;
            if (ADDRES) { float2 rv = rrow[tx + 25 * j]; v.x += rv.x; v.y += rv.y; }
            if (RELU)   { v.x = fmaxf(v.x, 0.f); v.y = fmaxf(v.y, 0.f); }
            yrow[tx + 25 * j] = v;
        }
    }
}

// ---------------- scores:  A[b] = P[b] P[b]^T  (no scale; folded into softmax) ----------------
// 128x128 tile, K=200 staged fully (Q plain, K transposed+padded). 256 threads, 8x8/thread.
__global__ void __launch_bounds__(256) scores_kernel(const float* __restrict__ P,
                                                     float* __restrict__ A)
{
    extern __shared__ char smem_raw[];
    float* Qs  = (float*)smem_raw;        // [128][200]
    float* KsT = Qs + SBM * DIM;          // [200][KT_STRIDE]

    const int b  = blockIdx.z;
    const int q0 = blockIdx.y * SBM;
    const int t0 = blockIdx.x * SBM;
    const float* Pb = P + (size_t)b * SEQ * DIM;
    const int tid = threadIdx.x;
    const int tx = tid % 16, ty = tid / 16;

    {   // stage Q (float4 coalesced)
        const float4* src = (const float4*)(Pb + (size_t)q0 * DIM);
        float4* dst = (float4*)Qs;
        for (int i = tid; i < SBM * (DIM / 4); i += 256) dst[i] = src[i];
    }
    // stage K transposed (coalesced gmem reads)
    for (int i = tid; i < SBM * DIM; i += 256) {
        int tt = i / DIM, d = i % DIM;
        KsT[d * KT_STRIDE + tt] = Pb[(size_t)(t0 + tt) * DIM + d];
    }
    __syncthreads();

    unsigned long long acc[8][4];
#pragma unroll
    for (int i = 0; i < 8; i++)
#pragma unroll
        for (int j = 0; j < 4; j++) acc[i][j] = 0ULL;

#pragma unroll 2
    for (int k = 0; k < DIM; k++) {
        unsigned long long a2[8];
#pragma unroll
        for (int i = 0; i < 8; i++) a2[i] = pack2(Qs[(ty + 16 * i) * DIM + k]);
        unsigned long long w[4];
#pragma unroll
        for (int j = 0; j < 4; j++)
            w[j] = *(const unsigned long long*)&KsT[k * KT_STRIDE + 2 * (tx + 16 * j)];
#pragma unroll
        for (int i = 0; i < 8; i++)
#pragma unroll
            for (int j = 0; j < 4; j++) acc[i][j] = ffma2(a2[i], w[j], acc[i][j]);
    }

    float* Ab = A + (size_t)b * SEQ * SEQ;
#pragma unroll
    for (int i = 0; i < 8; i++) {
        int q = q0 + ty + 16 * i;
        float2* row = (float2*)(Ab + (size_t)q * SEQ + t0);
#pragma unroll
        for (int j = 0; j < 4; j++) row[tx + 16 * j] = unpack2(acc[i][j]);
    }
}

// ---------------- row softmax with folded 1/sqrt(200) ----------------
__global__ void __launch_bounds__(128) softmax_kernel(float* __restrict__ A) {
    const size_t row = blockIdx.x;
    float4* p = (float4*)(A + row * SEQ);
    const int tid = threadIdx.x;
    const int lane = tid & 31, wid = tid >> 5;
    float4 v0 = p[tid];
    float4 v1 = p[tid + 128];

    float mx = fmaxf(fmaxf(fmaxf(v0.x, v0.y), fmaxf(v0.z, v0.w)),
                     fmaxf(fmaxf(v1.x, v1.y), fmaxf(v1.z, v1.w)));
#pragma unroll
    for (int o = 16; o; o >>= 1) mx = fmaxf(mx, __shfl_xor_sync(0xffffffffu, mx, o));
    __shared__ float smx[4], ssm[4];
    if (!lane) smx[wid] = mx;
    __syncthreads();
    float rmax = fmaxf(fmaxf(smx[0], smx[1]), fmaxf(smx[2], smx[3]));

    const float inv = 0.07071067811865475f; // 1/sqrt(200)
    v0.x = __expf((v0.x - rmax) * inv); v0.y = __expf((v0.y - rmax) * inv);
    v0.z = __expf((v0.z - rmax) * inv); v0.w = __expf((v0.w - rmax) * inv);
    v1.x = __expf((v1.x - rmax) * inv); v1.y = __expf((v1.y - rmax) * inv);
    v1.z = __expf((v1.z - rmax) * inv); v1.w = __expf((v1.w - rmax) * inv);
    float s = (v0.x + v0.y) + (v0.z + v0.w) + (v1.x + v1.y) + (v1.z + v1.w);
#pragma unroll
    for (int o = 16; o; o >>= 1) s += __shfl_xor_sync(0xffffffffu, s, o);
    if (!lane) ssm[wid] = s;
    __syncthreads();
    float dinv = 1.0f / (ssm[0] + ssm[1] + ssm[2] + ssm[3]);

    v0.x *= dinv; v0.y *= dinv; v0.z *= dinv; v0.w *= dinv;
    v1.x *= dinv; v1.y *= dinv; v1.z *= dinv; v1.w *= dinv;
    p[tid] = v0; p[tid + 128] = v1;
}

// ---------------- ln2d stats (per-batch mean/rstd over S*D) ----------------
__global__ void __launch_bounds__(512) ln_stats_kernel(const float* __restrict__ t,
                                                       float* __restrict__ stats) {
    const int b = blockIdx.x;
    const float4* p = (const float4*)(t + (size_t)b * SEQ * DIM);
    const int N4 = SEQ * DIM / 4; // 51200
    const int tid = threadIdx.x;
    const int lane = tid & 31, wid = tid >> 5;
    float s = 0.f, s2 = 0.f;
    for (int i = tid; i < N4; i += 512) {
        float4 v = p[i];
        s  += (v.x + v.y) + (v.z + v.w);
        s2 += v.x * v.x + v.y * v.y + v.z * v.z + v.w * v.w;
    }
#pragma unroll
    for (int o = 16; o; o >>= 1) {
        s  += __shfl_xor_sync(0xffffffffu, s, o);
        s2 += __shfl_xor_sync(0xffffffffu, s2, o);
    }
    __shared__ float sh[16], sh2[16];
    if (!lane) { sh[wid] = s; sh2[wid] = s2; }
    __syncthreads();
    if (tid == 0) {
        float S = 0.f, S2 = 0.f;
#pragma unroll
        for (int i = 0; i < 16; i++) { S += sh[i]; S2 += sh2[i]; }
        const float n = (float)(SEQ * DIM);
        float mean = S / n;
        float var  = S2 / n - mean * mean;
        stats[2 * b]     = mean;
        stats[2 * b + 1] = rsqrtf(var + LN_EPS);
    }
}

__global__ void ln_norm_kernel(const float4* __restrict__ t, const float* __restrict__ stats,
                               float4* __restrict__ h) {
    int g = blockIdx.x * blockDim.x + threadIdx.x;
    const int TOT = BATCH * SEQ * DIM / 4;
    if (g >= TOT) return;
    int b = g / (SEQ * DIM / 4);
    float m = stats[2 * b], r = stats[2 * b + 1];
    float4 v = t[g];
    h[g] = make_float4((v.x - m) * r, (v.y - m) * r, (v.z - m) * r, (v.w - m) * r);
}

// ---------------- final: out = ln(last row) @ Wd + bd (ln fused) ----------------
__global__ void final_kernel(const float* __restrict__ t, const float* __restrict__ stats,
                             const float* __restrict__ Wd, const float* __restrict__ bd,
                             float* __restrict__ out) {
    int b = blockIdx.x;
    int c = threadIdx.x;
    float m = stats[2 * b], rs = stats[2 * b + 1];
    const float* row = t + ((size_t)b * SEQ + (SEQ - 1)) * DIM;
    if (c < NCLS) {
        float acc = bd[c];
        for (int d = 0; d < DIM; d++)
            acc += (row[d] - m) * rs * Wd[d * NCLS + c];
        out[b * NCLS + c] = acc;
    }
}

// ---------------- host launcher ----------------
extern "C" void kernel_launch(void* const* d_in, const int* in_sizes, int n_in,
                              void* d_out, int out_size) {
    (void)in_sizes; (void)n_in; (void)out_size;
    const int*   x    = (const int*)  d_in[0];
    const float* emb  = (const float*)d_in[1];
    const float* pos  = (const float*)d_in[2];
    const float* Wp   = (const float*)d_in[3];
    const float* bp   = (const float*)d_in[4];
    const float* Wm   = (const float*)d_in[5];
    const float* bm   = (const float*)d_in[6];
    const float* W1   = (const float*)d_in[7];
    const float* b1   = (const float*)d_in[8];
    const float* W2   = (const float*)d_in[9];
    const float* b2   = (const float*)d_in[10];
    const float* Wd   = (const float*)d_in[11];
    const float* bd   = (const float*)d_in[12];
    float* out = (float*)d_out;

    float *h_, *p_, *c_, *A_, *We_, *st_;
    cudaGetSymbolAddress((void**)&h_,  g_h);
    cudaGetSymbolAddress((void**)&p_,  g_p);
    cudaGetSymbolAddress((void**)&c_,  g_c);
    cudaGetSymbolAddress((void**)&A_,  g_A);
    cudaGetSymbolAddress((void**)&We_, g_We);
    cudaGetSymbolAddress((void**)&st_, g_stats);

    const int SM_G50 = 64 * 50 * 4 + 50 * WPAD * 8;                  // 53600
    const int SM_G64 = 64 * 64 * 4 + 64 * WPAD * 8;                  // 68608
    const int SM_SC  = (SBM * DIM + DIM * KT_STRIDE) * 4;            // 206400
    cudaFuncSetAttribute(gemm200_kernel<50, false, false>, cudaFuncAttributeMaxDynamicSharedMemorySize, SM_G50);
    cudaFuncSetAttribute(gemm200_kernel<50, false, true >, cudaFuncAttributeMaxDynamicSharedMemorySize, SM_G50);
    cudaFuncSetAttribute(gemm200_kernel<50, true,  false>, cudaFuncAttributeMaxDynamicSharedMemorySize, SM_G50);
    cudaFuncSetAttribute(gemm200_kernel<64, false, false>, cudaFuncAttributeMaxDynamicSharedMemorySize, SM_G64);
    cudaFuncSetAttribute(scores_kernel, cudaFuncAttributeMaxDynamicSharedMemorySize, SM_SC);

    const long long RC = (long long)SEQ * DIM;       // 204800 per-batch row block
    const int ROWT = BATCH * SEQ / 64;               // 1024 row tiles (flat)
    const int ELT4 = BATCH * SEQ * DIM / 4;          // 3,276,800 float4s

    wmeff_kernel<<<(DIM * DIM + 255) / 256, 256>>>(Wm, We_);
    embed_kernel<<<(ELT4 + 255) / 256, 256>>>(x, (const float4*)emb, (const float4*)pos, (float4*)h_);

    for (int st = 0; st < 2; st++) {
        // p = h @ Wp + bp
        gemm200_kernel<50, false, false><<<dim3(ROWT, 1), 200, SM_G50>>>(
            h_, 0, Wp, 0, bp, nullptr, p_, 0, DIM);
        // A = p p^T (per batch)
        scores_kernel<<<dim3(SEQ / SBM, SEQ / SBM, BATCH), 256, SM_SC>>>(p_, A_);
        // softmax rows (scale folded)
        softmax_kernel<<<BATCH * SEQ, 128>>>(A_);
        // c = A @ p (batched: W = p per batch)
        gemm200_kernel<64, false, false><<<dim3(SEQ / 64, BATCH), 200, SM_G64>>>(
            A_, (long long)SEQ * SEQ, p_, RC, nullptr, nullptr, c_, RC, SEQ);
        // t = c @ WmEff + bm + h  -> p_
        gemm200_kernel<50, false, true><<<dim3(ROWT, 1), 200, SM_G50>>>(
            c_, 0, We_, 0, bm, h_, p_, 0, DIM);
        ln_stats_kernel<<<BATCH, 512>>>(p_, st_);
        ln_norm_kernel<<<(ELT4 + 255) / 256, 256>>>((const float4*)p_, st_, (float4*)h_);
        // ff1 = relu(h @ W1 + b1) -> c_
        gemm200_kernel<50, true, false><<<dim3(ROWT, 1), 200, SM_G50>>>(
            h_, 0, W1, 0, b1, nullptr, c_, 0, DIM);
        // t2 = ff1 @ W2 + b2 + h -> p_
        gemm200_kernel<50, false, true><<<dim3(ROWT, 1), 200, SM_G50>>>(
            c_, 0, W2, 0, b2, h_, p_, 0, DIM);
        ln_stats_kernel<<<BATCH, 512>>>(p_, st_);
        if (st == 0)
            ln_norm_kernel<<<(ELT4 + 255) / 256, 256>>>((const float4*)p_, st_, (float4*)h_);
    }
    // final ln2d fused into the tiny classifier GEMM (only row S-1 needed)
    final_kernel<<<BATCH, 32>>>(p_, st_, Wd, bd, out);
}

// round 5
// speedup vs baseline: 1.7259x; 1.7259x over previous
#include <cuda_runtime.h>
#include <cuda_bf16.h>
#include <math.h>
#include <stdint.h>

#define BATCH 64
#define SEQ   1024
#define DIM   200
#define NCLS  31
#define NHEAD 8
#define LN_EPS 1e-5f
#define ND2   (DIM/2)
#define WPAD  102
#define NPAD  224          /* padded N (d) for AP B operand */

// ---------------- scratch (static device memory; no allocations) ----------------
static __device__ float g_h [BATCH * SEQ * DIM];
static __device__ float g_p [BATCH * SEQ * DIM];             // tf32-rounded projection
static __device__ float g_c [BATCH * SEQ * DIM];
static __device__ float g_PT[(size_t)BATCH * NPAD * SEQ];    // [b][d][t], rows 200..223 stay 0
static __device__ float g_A [(size_t)BATCH * SEQ * SEQ];     // attention matrix
static __device__ float g_We[DIM * DIM];
static __device__ float g_stats[2 * BATCH];

// ================= helpers =================
__device__ __forceinline__ float tf32r(float x) {
    uint32_t r;
    asm("cvt.rna.tf32.f32 %0, %1;" : "=r"(r) : "f"(x));
    return __uint_as_float(r);
}

// legacy tensor-core MMA (valid on plain sm_100 target)
__device__ __forceinline__ void mma_tf32(float c[4], const uint32_t a[4], const uint32_t b[2]) {
    asm volatile(
        "mma.sync.aligned.m16n8k8.row.col.f32.tf32.tf32.f32 "
        "{%0,%1,%2,%3}, {%4,%5,%6,%7}, {%8,%9}, {%0,%1,%2,%3};"
        : "+f"(c[0]), "+f"(c[1]), "+f"(c[2]), "+f"(c[3])
        : "r"(a[0]), "r"(a[1]), "r"(a[2]), "r"(a[3]), "r"(b[0]), "r"(b[1]));
}

// f32x2 packed FMA helpers (FFMA2)
__device__ __forceinline__ unsigned long long pack2(float x) {
    unsigned long long r; asm("mov.b64 %0, {%1, %1};" : "=l"(r) : "f"(x)); return r;
}
__device__ __forceinline__ unsigned long long ffma2(unsigned long long a, unsigned long long b,
                                                    unsigned long long c) {
    unsigned long long d;
    asm("fma.rn.f32x2 %0, %1, %2, %3;" : "=l"(d) : "l"(a), "l"(b), "l"(c));
    return d;
}
__device__ __forceinline__ float2 unpack2(unsigned long long v) {
    float2 f; asm("mov.b64 {%0, %1}, %2;" : "=f"(f.x), "=f"(f.y) : "l"(v)); return f;
}

// ================= small kernels =================
__global__ void wmeff_kernel(const float* __restrict__ Wm, float* __restrict__ We) {
    int i = blockIdx.x * blockDim.x + threadIdx.x;
    if (i >= DIM * DIM) return;
    int row = i / DIM, col = i % DIM;
    float s = 0.f;
#pragma unroll
    for (int h = 0; h < NHEAD; h++) s += Wm[(h * DIM + row) * DIM + col];
    We[i] = s;
}

__global__ void embed_kernel(const int* __restrict__ x, const float4* __restrict__ emb,
                             const float4* __restrict__ pos, float4* __restrict__ h) {
    int g = blockIdx.x * blockDim.x + threadIdx.x;
    const int Q = DIM / 4;
    if (g >= BATCH * SEQ * Q) return;
    int q = g % Q;
    int r = g / Q;
    int s = r % SEQ;
    int tok = x[r];
    float4 e = emb[(size_t)tok * Q + q];
    float4 p = pos[(size_t)s * Q + q];
    h[g] = make_float4(e.x + p.x, e.y + p.y, e.z + p.z, e.w + p.w);
}

// transpose p[b][t][d] (stride 200) -> PT[b][d][t] (d < 200; rows >= 200 untouched = 0)
__global__ void transpose_kernel(const float* __restrict__ P, float* __restrict__ PT) {
    __shared__ float tile[32][33];
    int b = blockIdx.z, t0 = blockIdx.x * 32, d0 = blockIdx.y * 32;
    int tx = threadIdx.x, ty = threadIdx.y;
    const float* src = P + ((size_t)b * SEQ + t0) * DIM;
#pragma unroll
    for (int k = 0; k < 4; k++) {
        int r = ty + 8 * k;
        int d = d0 + tx;
        tile[r][tx] = (d < DIM) ? src[r * DIM + d] : 0.f;
    }
    __syncthreads();
    float* dst = PT + (size_t)b * NPAD * SEQ;
#pragma unroll
    for (int k = 0; k < 4; k++) {
        int d = d0 + ty + 8 * k;
        if (d < DIM) dst[(size_t)d * SEQ + t0 + tx] = tile[tx][ty + 8 * k];
    }
}

// ================= FFMA2 GEMM (X @ W + bias [+res][relu][tf32out]) =================
template <int BK, bool RELU, bool ADDRES, bool TF32OUT>
__global__ void __launch_bounds__(200) gemm200_kernel(
    const float* __restrict__ X,
    const float* __restrict__ W,
    const float* __restrict__ bias,
    const float* __restrict__ res,
    float* __restrict__ Y,
    int K)
{
    extern __shared__ char smem_raw[];
    float*  As = (float*)smem_raw;
    float2* Ws = (float2*)(smem_raw + 64 * BK * sizeof(float));

    const long long row0 = (long long)blockIdx.x * 64;
    const float* Xb = X + row0 * K;
    const int tid = threadIdx.x;
    const int tx = tid % 25;
    const int ty = tid / 25;

    unsigned long long acc[8][4];
#pragma unroll
    for (int i = 0; i < 8; i++)
#pragma unroll
        for (int j = 0; j < 4; j++) acc[i][j] = 0ULL;

    for (int k0 = 0; k0 < K; k0 += BK) {
        for (int i = tid; i < 64 * BK; i += 200) {
            int r = i / BK, c = i % BK;
            As[i] = Xb[(long long)r * K + k0 + c];
        }
        for (int i = tid; i < BK * ND2; i += 200) {
            int kk = i / ND2, n2 = i % ND2;
            Ws[kk * WPAD + n2] = ((const float2*)(W + (long long)(k0 + kk) * DIM))[n2];
        }
        __syncthreads();
#pragma unroll 2
        for (int k = 0; k < BK; k++) {
            unsigned long long a2[8];
#pragma unroll
            for (int i = 0; i < 8; i++) a2[i] = pack2(As[(ty + 8 * i) * BK + k]);
            unsigned long long w[4];
#pragma unroll
            for (int j = 0; j < 4; j++)
                w[j] = *(const unsigned long long*)&Ws[k * WPAD + tx + 25 * j];
#pragma unroll
            for (int i = 0; i < 8; i++)
#pragma unroll
                for (int j = 0; j < 4; j++) acc[i][j] = ffma2(a2[i], w[j], acc[i][j]);
        }
        __syncthreads();
    }

    float2 bb[4];
#pragma unroll
    for (int j = 0; j < 4; j++) bb[j] = ((const float2*)bias)[tx + 25 * j];

#pragma unroll
    for (int i = 0; i < 8; i++) {
        size_t grow = (size_t)(row0 + ty + 8 * i) * DIM;
        float2* yrow = (float2*)(Y + grow);
        const float2* rrow = ADDRES ? (const float2*)(res + grow) : (const float2*)0;
#pragma unroll
        for (int j = 0; j < 4; j++) {
            float2 v = unpack2(acc[i][j]);
            v.x += bb[j].x; v.y += bb[j].y;
            if (ADDRES) { float2 rv = rrow[tx + 25 * j]; v.x += rv.x; v.y += rv.y; }
            if (RELU)   { v.x = fmaxf(v.x, 0.f); v.y = fmaxf(v.y, 0.f); }
            if (TF32OUT){ v.x = tf32r(v.x); v.y = tf32r(v.y); }
            yrow[tx + 25 * j] = v;
        }
    }
}

// ================= tf32 MMA scores: A[b] = P[b] P[b]^T  (tile 128x128, K=200) =================
#define SC_LD 204   /* padded smem row stride (floats); 204 % 32 = 12 -> conflict-free */

__global__ void __launch_bounds__(256) scores_mma_kernel(const float* __restrict__ P,
                                                         float* __restrict__ A) {
    extern __shared__ float smem[];
    float* Qs = smem;                 // [128][204]
    float* Ks = smem + 128 * SC_LD;   // [128][204]

    const int b = blockIdx.z, s0 = blockIdx.y * 128, t0 = blockIdx.x * 128;
    const float* Pb = P + (size_t)b * SEQ * DIM;
    const int tid = threadIdx.x;

    for (int idx = tid; idx < 128 * 50; idx += 256) {
        int row = idx / 50, c4 = idx % 50;
        ((float4*)(Qs + row * SC_LD))[c4] = ((const float4*)(Pb + (size_t)(s0 + row) * DIM))[c4];
        ((float4*)(Ks + row * SC_LD))[c4] = ((const float4*)(Pb + (size_t)(t0 + row) * DIM))[c4];
    }
    __syncthreads();

    const int warp = tid >> 5, lane = tid & 31;
    const int gid = lane >> 2, tig = lane & 3;
    const int m0 = (warp & 3) * 32;     // warp tile: 32 (M) x 64 (N)
    const int n0 = (warp >> 2) * 64;

    float c[2][8][4];
#pragma unroll
    for (int mt = 0; mt < 2; mt++)
#pragma unroll
        for (int nt = 0; nt < 8; nt++)
#pragma unroll
            for (int q = 0; q < 4; q++) c[mt][nt][q] = 0.f;

#pragma unroll 5
    for (int ks = 0; ks < 25; ks++) {
        const int k0 = ks * 8;
        uint32_t a[2][4];
#pragma unroll
        for (int mt = 0; mt < 2; mt++) {
            const float* qr = Qs + (m0 + mt * 16 + gid) * SC_LD + k0 + tig;
            a[mt][0] = __float_as_uint(qr[0]);
            a[mt][1] = __float_as_uint(qr[8 * SC_LD]);
            a[mt][2] = __float_as_uint(qr[4]);
            a[mt][3] = __float_as_uint(qr[8 * SC_LD + 4]);
        }
#pragma unroll
        for (int nt = 0; nt < 8; nt++) {
            const float* kr = Ks + (n0 + nt * 8 + gid) * SC_LD + k0 + tig;
            uint32_t bfr[2];
            bfr[0] = __float_as_uint(kr[0]);
            bfr[1] = __float_as_uint(kr[4]);
            mma_tf32(c[0][nt], a[0], bfr);
            mma_tf32(c[1][nt], a[1], bfr);
        }
    }

    float* Ab = A + ((size_t)b << 20);
#pragma unroll
    for (int mt = 0; mt < 2; mt++) {
        int r0 = s0 + m0 + mt * 16 + gid;
#pragma unroll
        for (int nt = 0; nt < 8; nt++) {
            int col = t0 + n0 + nt * 8 + 2 * tig;
            *(float2*)(Ab + (size_t)r0 * SEQ + col)       = make_float2(c[mt][nt][0], c[mt][nt][1]);
            *(float2*)(Ab + (size_t)(r0 + 8) * SEQ + col) = make_float2(c[mt][nt][2], c[mt][nt][3]);
        }
    }
}

// ================= tf32 MMA AP: c[b] = A[b] @ P[b]  (tile 128x224, K=1024) =================
#define AP_BK 64
#define AP_LD 68    /* 68 % 32 = 4 -> conflict-free fragment loads */

__global__ void __launch_bounds__(256) ap_mma_kernel(const float* __restrict__ A,
                                                     const float* __restrict__ PT,
                                                     float* __restrict__ C) {
    extern __shared__ float smem[];
    float* As = smem;                  // [128][68]
    float* Bs = smem + 128 * AP_LD;    // [224][68]

    const int b = blockIdx.y, s0 = blockIdx.x * 128;
    const float* Ab = A + ((size_t)b << 20) + (size_t)s0 * SEQ;
    const float* PTb = PT + (size_t)b * NPAD * SEQ;
    const int tid = threadIdx.x;
    const int warp = tid >> 5, lane = tid & 31;
    const int gid = lane >> 2, tig = lane & 3;
    const int m0 = (warp & 3) * 32;      // warp tile: 32 (M) x 112 (N)
    const int n0 = (warp >> 2) * 112;

    float c[2][14][4];
#pragma unroll
    for (int mt = 0; mt < 2; mt++)
#pragma unroll
        for (int nt = 0; nt < 14; nt++)
#pragma unroll
            for (int q = 0; q < 4; q++) c[mt][nt][q] = 0.f;

    for (int ch = 0; ch < 16; ch++) {
        const int k0 = ch * AP_BK;
        for (int idx = tid; idx < 128 * 16; idx += 256) {
            int row = idx >> 4, c4 = idx & 15;
            ((float4*)(As + row * AP_LD))[c4] =
                ((const float4*)(Ab + (size_t)row * SEQ + k0))[c4];
        }
        for (int idx = tid; idx < 224 * 16; idx += 256) {
            int row = idx >> 4, c4 = idx & 15;
            ((float4*)(Bs + row * AP_LD))[c4] =
                ((const float4*)(PTb + (size_t)row * SEQ + k0))[c4];
        }
        __syncthreads();

#pragma unroll
        for (int ks = 0; ks < 8; ks++) {
            const int k = ks * 8;
            uint32_t a[2][4];
#pragma unroll
            for (int mt = 0; mt < 2; mt++) {
                const float* ar = As + (m0 + mt * 16 + gid) * AP_LD + k + tig;
                a[mt][0] = __float_as_uint(ar[0]);
                a[mt][1] = __float_as_uint(ar[8 * AP_LD]);
                a[mt][2] = __float_as_uint(ar[4]);
                a[mt][3] = __float_as_uint(ar[8 * AP_LD + 4]);
            }
#pragma unroll
            for (int nt = 0; nt < 14; nt++) {
                const float* br = Bs + (n0 + nt * 8 + gid) * AP_LD + k + tig;
                uint32_t bfr[2];
                bfr[0] = __float_as_uint(br[0]);
                bfr[1] = __float_as_uint(br[4]);
                mma_tf32(c[0][nt], a[0], bfr);
                mma_tf32(c[1][nt], a[1], bfr);
            }
        }
        __syncthreads();
    }

    float* Cb = C + ((size_t)b * SEQ + s0) * DIM;
#pragma unroll
    for (int mt = 0; mt < 2; mt++) {
        int r0 = m0 + mt * 16 + gid;
#pragma unroll
        for (int nt = 0; nt < 14; nt++) {
            int col = n0 + nt * 8 + 2 * tig;
            if (col < DIM) {
                *(float2*)(Cb + (size_t)r0 * DIM + col)       = make_float2(c[mt][nt][0], c[mt][nt][1]);
                *(float2*)(Cb + (size_t)(r0 + 8) * DIM + col) = make_float2(c[mt][nt][2], c[mt][nt][3]);
            }
        }
    }
}

// ================= softmax (scale folded, output tf32-rounded) =================
__global__ void __launch_bounds__(128) softmax_kernel(float* __restrict__ A) {
    const size_t row = blockIdx.x;
    float4* p = (float4*)(A + row * SEQ);
    const int tid = threadIdx.x;
    const int lane = tid & 31, wid = tid >> 5;
    float4 v0 = p[tid];
    float4 v1 = p[tid + 128];

    float mx = fmaxf(fmaxf(fmaxf(v0.x, v0.y), fmaxf(v0.z, v0.w)),
                     fmaxf(fmaxf(v1.x, v1.y), fmaxf(v1.z, v1.w)));
#pragma unroll
    for (int o = 16; o; o >>= 1) mx = fmaxf(mx, __shfl_xor_sync(0xffffffffu, mx, o));
    __shared__ float smx[4], ssm[4];
    if (!lane) smx[wid] = mx;
    __syncthreads();
    float rmax = fmaxf(fmaxf(smx[0], smx[1]), fmaxf(smx[2], smx[3]));

    const float inv = 0.07071067811865475f; // 1/sqrt(200)
    v0.x = __expf((v0.x - rmax) * inv); v0.y = __expf((v0.y - rmax) * inv);
    v0.z = __expf((v0.z - rmax) * inv); v0.w = __expf((v0.w - rmax) * inv);
    v1.x = __expf((v1.x - rmax) * inv); v1.y = __expf((v1.y - rmax) * inv);
    v1.z = __expf((v1.z - rmax) * inv); v1.w = __expf((v1.w - rmax) * inv);
    float s = (v0.x + v0.y) + (v0.z + v0.w) + (v1.x + v1.y) + (v1.z + v1.w);
#pragma unroll
    for (int o = 16; o; o >>= 1) s += __shfl_xor_sync(0xffffffffu, s, o);
    if (!lane) ssm[wid] = s;
    __syncthreads();
    float dinv = 1.0f / (ssm[0] + ssm[1] + ssm[2] + ssm[3]);

    v0.x = tf32r(v0.x * dinv); v0.y = tf32r(v0.y * dinv);
    v0.z = tf32r(v0.z * dinv); v0.w = tf32r(v0.w * dinv);
    v1.x = tf32r(v1.x * dinv); v1.y = tf32r(v1.y * dinv);
    v1.z = tf32r(v1.z * dinv); v1.w = tf32r(v1.w * dinv);
    p[tid] = v0; p[tid + 128] = v1;
}

// ================= ln2d =================
__global__ void __launch_bounds__(512) ln_stats_kernel(const float* __restrict__ t,
                                                       float* __restrict__ stats) {
    const int b = blockIdx.x;
    const float4* p = (const float4*)(t + (size_t)b * SEQ * DIM);
    const int N4 = SEQ * DIM / 4;
    const int tid = threadIdx.x;
    const int lane = tid & 31, wid = tid >> 5;
    float s = 0.f, s2 = 0.f;
    for (int i = tid; i < N4; i += 512) {
        float4 v = p[i];
        s  += (v.x + v.y) + (v.z + v.w);
        s2 += v.x * v.x + v.y * v.y + v.z * v.z + v.w * v.w;
    }
#pragma unroll
    for (int o = 16; o; o >>= 1) {
        s  += __shfl_xor_sync(0xffffffffu, s, o);
        s2 += __shfl_xor_sync(0xffffffffu, s2, o);
    }
    __shared__ float sh[16], sh2[16];
    if (!lane) { sh[wid] = s; sh2[wid] = s2; }
    __syncthreads();
    if (tid == 0) {
        float S = 0.f, S2 = 0.f;
#pragma unroll
        for (int i = 0; i < 16; i++) { S += sh[i]; S2 += sh2[i]; }
        const float n = (float)(SEQ * DIM);
        float mean = S / n;
        float var  = S2 / n - mean * mean;
        stats[2 * b]     = mean;
        stats[2 * b + 1] = rsqrtf(var + LN_EPS);
    }
}

__global__ void ln_norm_kernel(const float4* __restrict__ t, const float* __restrict__ stats,
                               float4* __restrict__ h) {
    int g = blockIdx.x * blockDim.x + threadIdx.x;
    const int TOT = BATCH * SEQ * DIM / 4;
    if (g >= TOT) return;
    int b = g / (SEQ * DIM / 4);
    float m = stats[2 * b], r = stats[2 * b + 1];
    float4 v = t[g];
    h[g] = make_float4((v.x - m) * r, (v.y - m) * r, (v.z - m) * r, (v.w - m) * r);
}

__global__ void final_kernel(const float* __restrict__ t, const float* __restrict__ stats,
                             const float* __restrict__ Wd, const float* __restrict__ bd,
                             float* __restrict__ out) {
    int b = blockIdx.x;
    int c = threadIdx.x;
    float m = stats[2 * b], rs = stats[2 * b + 1];
    const float* row = t + ((size_t)b * SEQ + (SEQ - 1)) * DIM;
    if (c < NCLS) {
        float acc = bd[c];
        for (int d = 0; d < DIM; d++)
            acc += (row[d] - m) * rs * Wd[d * NCLS + c];
        out[b * NCLS + c] = acc;
    }
}

// ================= host launcher =================
extern "C" void kernel_launch(void* const* d_in, const int* in_sizes, int n_in,
                              void* d_out, int out_size) {
    (void)in_sizes; (void)n_in; (void)out_size;
    const int*   x    = (const int*)  d_in[0];
    const float* emb  = (const float*)d_in[1];
    const float* pos  = (const float*)d_in[2];
    const float* Wp   = (const float*)d_in[3];
    const float* bp   = (const float*)d_in[4];
    const float* Wm   = (const float*)d_in[5];
    const float* bm   = (const float*)d_in[6];
    const float* W1   = (const float*)d_in[7];
    const float* b1   = (const float*)d_in[8];
    const float* W2   = (const float*)d_in[9];
    const float* b2   = (const float*)d_in[10];
    const float* Wd   = (const float*)d_in[11];
    const float* bd   = (const float*)d_in[12];
    float* out = (float*)d_out;

    float *h_, *p_, *c_, *PT_, *A_, *We_, *st_;
    cudaGetSymbolAddress((void**)&h_,  g_h);
    cudaGetSymbolAddress((void**)&p_,  g_p);
    cudaGetSymbolAddress((void**)&c_,  g_c);
    cudaGetSymbolAddress((void**)&PT_, g_PT);
    cudaGetSymbolAddress((void**)&A_,  g_A);
    cudaGetSymbolAddress((void**)&We_, g_We);
    cudaGetSymbolAddress((void**)&st_, g_stats);

    const int SM_G50 = 64 * 50 * 4 + 50 * WPAD * 8;               // 53600
    const int SM_SC  = 2 * 128 * SC_LD * 4;                       // 208896
    const int SM_AP  = (128 + 224) * AP_LD * 4;                   // 95744
    cudaFuncSetAttribute(gemm200_kernel<50, false, false, true >, cudaFuncAttributeMaxDynamicSharedMemorySize, SM_G50);
    cudaFuncSetAttribute(gemm200_kernel<50, false, true,  false>, cudaFuncAttributeMaxDynamicSharedMemorySize, SM_G50);
    cudaFuncSetAttribute(gemm200_kernel<50, true,  false, false>, cudaFuncAttributeMaxDynamicSharedMemorySize, SM_G50);
    cudaFuncSetAttribute(scores_mma_kernel, cudaFuncAttributeMaxDynamicSharedMemorySize, SM_SC);
    cudaFuncSetAttribute(ap_mma_kernel,     cudaFuncAttributeMaxDynamicSharedMemorySize, SM_AP);

    const int ROWT = BATCH * SEQ / 64;               // 1024 row tiles
    const int ELT4 = BATCH * SEQ * DIM / 4;

    wmeff_kernel<<<(DIM * DIM + 255) / 256, 256>>>(Wm, We_);
    embed_kernel<<<(ELT4 + 255) / 256, 256>>>(x, (const float4*)emb, (const float4*)pos, (float4*)h_);

    for (int st = 0; st < 2; st++) {
        // p = tf32(h @ Wp + bp)
        gemm200_kernel<50, false, false, true><<<ROWT, 200, SM_G50>>>(
            h_, Wp, bp, nullptr, p_, DIM);
        // PT[b][d][t] = p[b][t][d]
        transpose_kernel<<<dim3(SEQ / 32, 7, BATCH), dim3(32, 8)>>>(p_, PT_);
        // A = P P^T (tf32 mma.sync)
        scores_mma_kernel<<<dim3(SEQ / 128, SEQ / 128, BATCH), 256, SM_SC>>>(p_, A_);
        // softmax rows (scale folded, tf32-rounded output)
        softmax_kernel<<<BATCH * SEQ, 128>>>(A_);
        // c = A @ p (tf32 mma.sync)
        ap_mma_kernel<<<dim3(SEQ / 128, BATCH), 256, SM_AP>>>(A_, PT_, c_);
        // t = c @ WmEff + bm + h -> p_
        gemm200_kernel<50, false, true, false><<<ROWT, 200, SM_G50>>>(
            c_, We_, bm, h_, p_, DIM);
        ln_stats_kernel<<<BATCH, 512>>>(p_, st_);
        ln_norm_kernel<<<(ELT4 + 255) / 256, 256>>>((const float4*)p_, st_, (float4*)h_);
        // ff1 = relu(h @ W1 + b1) -> c_
        gemm200_kernel<50, true, false, false><<<ROWT, 200, SM_G50>>>(
            h_, W1, b1, nullptr, c_, DIM);
        // t2 = ff1 @ W2 + b2 + h -> p_
        gemm200_kernel<50, false, true, false><<<ROWT, 200, SM_G50>>>(
            c_, W2, b2, h_, p_, DIM);
        ln_stats_kernel<<<BATCH, 512>>>(p_, st_);
        if (st == 0)
            ln_norm_kernel<<<(ELT4 + 255) / 256, 256>>>((const float4*)p_, st_, (float4*)h_);
    }
    final_kernel<<<BATCH, 32>>>(p_, st_, Wd, bd, out);
}

// round 6
// speedup vs baseline: 2.0852x; 1.2081x over previous
#include <cuda_runtime.h>
#include <cuda_bf16.h>
#include <math.h>
#include <stdint.h>

#define BATCH 64
#define SEQ   1024
#define DIM   200
#define NCLS  31
#define NHEAD 8
#define LN_EPS 1e-5f
#define NPAD  224          /* padded N for B operands */

// ---------------- scratch (static device memory; no allocations) ----------------
static __device__ float g_h [BATCH * SEQ * DIM];             // embed / t2 (trunk)
static __device__ float g_t [BATCH * SEQ * DIM];             // pre-LN mid trunk
static __device__ float g_p [BATCH * SEQ * DIM];             // tf32-rounded projection
static __device__ float g_c [BATCH * SEQ * DIM];             // attn out / ff1
static __device__ float g_PT[(size_t)BATCH * NPAD * SEQ];    // [b][d][t], rows 200..223 stay 0
static __device__ float g_A [(size_t)BATCH * SEQ * SEQ];     // attention matrix
static __device__ float g_WT[4 * NPAD * DIM];                // transposed weights [n][k]
static __device__ float g_stats[4 * BATCH];                  // st1 (0..127), st2 (128..255)

// ================= helpers =================
__device__ __forceinline__ float tf32r(float x) {
    uint32_t r;
    asm("cvt.rna.tf32.f32 %0, %1;" : "=r"(r) : "f"(x));
    return __uint_as_float(r);
}

__device__ __forceinline__ void mma_tf32(float c[4], const uint32_t a[4], const uint32_t b[2]) {
    asm volatile(
        "mma.sync.aligned.m16n8k8.row.col.f32.tf32.tf32.f32 "
        "{%0,%1,%2,%3}, {%4,%5,%6,%7}, {%8,%9}, {%0,%1,%2,%3};"
        : "+f"(c[0]), "+f"(c[1]), "+f"(c[2]), "+f"(c[3])
        : "r"(a[0]), "r"(a[1]), "r"(a[2]), "r"(a[3]), "r"(b[0]), "r"(b[1]));
}

// ================= small kernels =================
// build transposed (and head-collapsed) weights, zero-padded to 224 rows
__global__ void wprep_kernel(const float* __restrict__ Wp, const float* __restrict__ Wm,
                             const float* __restrict__ W1, const float* __restrict__ W2,
                             float* __restrict__ WT) {
    int i = blockIdx.x * blockDim.x + threadIdx.x;
    if (i >= NPAD * DIM) return;
    int n = i / DIM, k = i % DIM;
    int which = blockIdx.y;
    float v = 0.f;
    if (n < DIM) {
        if (which == 0) v = Wp[k * DIM + n];
        else if (which == 1) {
#pragma unroll
            for (int h = 0; h < NHEAD; h++) v += Wm[(h * DIM + k) * DIM + n];
        } else if (which == 2) v = W1[k * DIM + n];
        else v = W2[k * DIM + n];
    }
    WT[which * NPAD * DIM + i] = v;
}

__global__ void embed_kernel(const int* __restrict__ x, const float4* __restrict__ emb,
                             const float4* __restrict__ pos, float4* __restrict__ h) {
    int g = blockIdx.x * blockDim.x + threadIdx.x;
    const int Q = DIM / 4;
    if (g >= BATCH * SEQ * Q) return;
    int q = g % Q;
    int r = g / Q;
    int s = r % SEQ;
    int tok = x[r];
    float4 e = emb[(size_t)tok * Q + q];
    float4 p = pos[(size_t)s * Q + q];
    h[g] = make_float4(e.x + p.x, e.y + p.y, e.z + p.z, e.w + p.w);
}

// transpose p[b][t][d] -> PT[b][d][t]
__global__ void transpose_kernel(const float* __restrict__ P, float* __restrict__ PT) {
    __shared__ float tile[32][33];
    int b = blockIdx.z, t0 = blockIdx.x * 32, d0 = blockIdx.y * 32;
    int tx = threadIdx.x, ty = threadIdx.y;
    const float* src = P + ((size_t)b * SEQ + t0) * DIM;
#pragma unroll
    for (int k = 0; k < 4; k++) {
        int r = ty + 8 * k;
        int d = d0 + tx;
        tile[r][tx] = (d < DIM) ? src[r * DIM + d] : 0.f;
    }
    __syncthreads();
    float* dst = PT + (size_t)b * NPAD * SEQ;
#pragma unroll
    for (int k = 0; k < 4; k++) {
        int d = d0 + ty + 8 * k;
        if (d < DIM) dst[(size_t)d * SEQ + t0 + tx] = tile[tx][ty + 8 * k];
    }
}

// ============ layer GEMM (tf32 mma): Y = op( lnA(X) @ W + bias [+ lnR(res)] ) ============
// CTA: 128 rows x 224 cols (N=200 valid), K=200 in 5 chunks of 40.
// TERMS=3 -> 3xTF32 (hi/lo split), precision ~fp32.
#define LG_LD 44

template <bool RELU, bool ADDRES, bool TF32OUT, bool ALN, bool RESLN, int TERMS>
__global__ void __launch_bounds__(256) lgemm_kernel(
    const float* __restrict__ X,
    const float* __restrict__ WT,        // [224][200] transposed weights
    const float* __restrict__ bias,
    const float* __restrict__ res,
    const float* __restrict__ statsA,
    const float* __restrict__ statsR,
    float* __restrict__ Y)
{
    extern __shared__ float smem[];
    float* As = smem;                  // [128][44]
    float* Bs = smem + 128 * LG_LD;    // [224][44]

    const int row0 = blockIdx.x * 128;
    const int b = blockIdx.x >> 3;     // 8 CTAs per batch (1024/128)
    const float4* X4 = (const float4*)(X + (size_t)row0 * DIM);
    const float4* W4 = (const float4*)WT;
    const int tid = threadIdx.x;
    const int warp = tid >> 5, lane = tid & 31;
    const int gid = lane >> 2, tig = lane & 3;
    const int m0 = (warp & 3) * 32;
    const int n0 = (warp >> 2) * 112;

    float mA = 0.f, rA = 1.f;
    if (ALN) { mA = statsA[2 * b]; rA = statsA[2 * b + 1]; }

    float c[2][14][4];
#pragma unroll
    for (int mt = 0; mt < 2; mt++)
#pragma unroll
        for (int nt = 0; nt < 14; nt++)
#pragma unroll
            for (int q = 0; q < 4; q++) c[mt][nt][q] = 0.f;

#pragma unroll
    for (int ch = 0; ch < 5; ch++) {
        const int k0 = ch * 40;
        // stage A (optionally layer-normalized)
#pragma unroll
        for (int it = 0; it < 5; it++) {
            int idx = tid + it * 256;          // 1280 total
            int row = idx / 10, c4 = idx % 10;
            float4 v = X4[(size_t)row * 50 + (k0 >> 2) + c4];
            if (ALN) {
                v.x = (v.x - mA) * rA; v.y = (v.y - mA) * rA;
                v.z = (v.z - mA) * rA; v.w = (v.w - mA) * rA;
            }
            *(float4*)(As + row * LG_LD + c4 * 4) = v;
        }
        // stage B
        for (int idx = tid; idx < 224 * 10; idx += 256) {
            int row = idx / 10, c4 = idx % 10;
            *(float4*)(Bs + row * LG_LD + c4 * 4) = W4[(size_t)row * 50 + (k0 >> 2) + c4];
        }
        __syncthreads();

#pragma unroll
        for (int ks = 0; ks < 5; ks++) {
            const int k = ks * 8;
            uint32_t ahi[2][4], alo[2][4];
#pragma unroll
            for (int mt = 0; mt < 2; mt++) {
                const float* ar = As + (m0 + mt * 16 + gid) * LG_LD + k + tig;
                float a0 = ar[0], a1 = ar[8 * LG_LD], a2 = ar[4], a3 = ar[8 * LG_LD + 4];
                float h0 = tf32r(a0), h1 = tf32r(a1), h2 = tf32r(a2), h3 = tf32r(a3);
                ahi[mt][0] = __float_as_uint(h0); ahi[mt][1] = __float_as_uint(h1);
                ahi[mt][2] = __float_as_uint(h2); ahi[mt][3] = __float_as_uint(h3);
                if (TERMS == 3) {
                    alo[mt][0] = __float_as_uint(a0 - h0);
                    alo[mt][1] = __float_as_uint(a1 - h1);
                    alo[mt][2] = __float_as_uint(a2 - h2);
                    alo[mt][3] = __float_as_uint(a3 - h3);
                }
            }
#pragma unroll
            for (int nt = 0; nt < 14; nt++) {
                const float* br = Bs + (n0 + nt * 8 + gid) * LG_LD + k + tig;
                float b0 = br[0], b1 = br[4];
                float bh0 = tf32r(b0), bh1 = tf32r(b1);
                uint32_t bhi[2] = { __float_as_uint(bh0), __float_as_uint(bh1) };
                if (TERMS == 3) {
                    uint32_t blo[2] = { __float_as_uint(b0 - bh0), __float_as_uint(b1 - bh1) };
#pragma unroll
                    for (int mt = 0; mt < 2; mt++) {
                        mma_tf32(c[mt][nt], ahi[mt], blo);
                        mma_tf32(c[mt][nt], alo[mt], bhi);
                        mma_tf32(c[mt][nt], ahi[mt], bhi);
                    }
                } else {
#pragma unroll
                    for (int mt = 0; mt < 2; mt++) mma_tf32(c[mt][nt], ahi[mt], bhi);
                }
            }
        }
        __syncthreads();
    }

    float mR = 0.f, rR = 1.f;
    if (RESLN) { mR = statsR[2 * b]; rR = statsR[2 * b + 1]; }

    float* Yb = Y + (size_t)row0 * DIM;
    const float* Rb = ADDRES ? (res + (size_t)row0 * DIM) : (const float*)0;
#pragma unroll
    for (int mt = 0; mt < 2; mt++) {
        int r0 = m0 + mt * 16 + gid;
#pragma unroll
        for (int nt = 0; nt < 14; nt++) {
            int col = n0 + nt * 8 + 2 * tig;
            if (col < DIM) {
                float bx = bias[col], by = bias[col + 1];
                float v0 = c[mt][nt][0] + bx, v1 = c[mt][nt][1] + by;
                float v2 = c[mt][nt][2] + bx, v3 = c[mt][nt][3] + by;
                if (ADDRES) {
                    float q0 = Rb[(size_t)r0 * DIM + col],       q1 = Rb[(size_t)r0 * DIM + col + 1];
                    float q2 = Rb[(size_t)(r0 + 8) * DIM + col], q3 = Rb[(size_t)(r0 + 8) * DIM + col + 1];
                    if (RESLN) {
                        q0 = (q0 - mR) * rR; q1 = (q1 - mR) * rR;
                        q2 = (q2 - mR) * rR; q3 = (q3 - mR) * rR;
                    }
                    v0 += q0; v1 += q1; v2 += q2; v3 += q3;
                }
                if (RELU) {
                    v0 = fmaxf(v0, 0.f); v1 = fmaxf(v1, 0.f);
                    v2 = fmaxf(v2, 0.f); v3 = fmaxf(v3, 0.f);
                }
                if (TF32OUT) {
                    v0 = tf32r(v0); v1 = tf32r(v1); v2 = tf32r(v2); v3 = tf32r(v3);
                }
                *(float2*)(Yb + (size_t)r0 * DIM + col)       = make_float2(v0, v1);
                *(float2*)(Yb + (size_t)(r0 + 8) * DIM + col) = make_float2(v2, v3);
            }
        }
    }
}

// ================= tf32 MMA scores: A[b] = P[b] P[b]^T  (tile 128x128, K=200) =================
#define SC_LD 204

__global__ void __launch_bounds__(256) scores_mma_kernel(const float* __restrict__ P,
                                                         float* __restrict__ A) {
    extern __shared__ float smem[];
    float* Qs = smem;
    float* Ks = smem + 128 * SC_LD;

    const int b = blockIdx.z, s0 = blockIdx.y * 128, t0 = blockIdx.x * 128;
    const float* Pb = P + (size_t)b * SEQ * DIM;
    const int tid = threadIdx.x;

    for (int idx = tid; idx < 128 * 50; idx += 256) {
        int row = idx / 50, c4 = idx % 50;
        ((float4*)(Qs + row * SC_LD))[c4] = ((const float4*)(Pb + (size_t)(s0 + row) * DIM))[c4];
        ((float4*)(Ks + row * SC_LD))[c4] = ((const float4*)(Pb + (size_t)(t0 + row) * DIM))[c4];
    }
    __syncthreads();

    const int warp = tid >> 5, lane = tid & 31;
    const int gid = lane >> 2, tig = lane & 3;
    const int m0 = (warp & 3) * 32;
    const int n0 = (warp >> 2) * 64;

    float c[2][8][4];
#pragma unroll
    for (int mt = 0; mt < 2; mt++)
#pragma unroll
        for (int nt = 0; nt < 8; nt++)
#pragma unroll
            for (int q = 0; q < 4; q++) c[mt][nt][q] = 0.f;

#pragma unroll 5
    for (int ks = 0; ks < 25; ks++) {
        const int k0 = ks * 8;
        uint32_t a[2][4];
#pragma unroll
        for (int mt = 0; mt < 2; mt++) {
            const float* qr = Qs + (m0 + mt * 16 + gid) * SC_LD + k0 + tig;
            a[mt][0] = __float_as_uint(qr[0]);
            a[mt][1] = __float_as_uint(qr[8 * SC_LD]);
            a[mt][2] = __float_as_uint(qr[4]);
            a[mt][3] = __float_as_uint(qr[8 * SC_LD + 4]);
        }
#pragma unroll
        for (int nt = 0; nt < 8; nt++) {
            const float* kr = Ks + (n0 + nt * 8 + gid) * SC_LD + k0 + tig;
            uint32_t bfr[2];
            bfr[0] = __float_as_uint(kr[0]);
            bfr[1] = __float_as_uint(kr[4]);
            mma_tf32(c[0][nt], a[0], bfr);
            mma_tf32(c[1][nt], a[1], bfr);
        }
    }

    float* Ab = A + ((size_t)b << 20);
#pragma unroll
    for (int mt = 0; mt < 2; mt++) {
        int r0 = s0 + m0 + mt * 16 + gid;
#pragma unroll
        for (int nt = 0; nt < 8; nt++) {
            int col = t0 + n0 + nt * 8 + 2 * tig;
            *(float2*)(Ab + (size_t)r0 * SEQ + col)       = make_float2(c[mt][nt][0], c[mt][nt][1]);
            *(float2*)(Ab + (size_t)(r0 + 8) * SEQ + col) = make_float2(c[mt][nt][2], c[mt][nt][3]);
        }
    }
}

// ================= tf32 MMA AP: c[b] = A[b] @ P[b]  (tile 128x224, K=1024) =================
#define AP_BK 64
#define AP_LD 68

__global__ void __launch_bounds__(256) ap_mma_kernel(const float* __restrict__ A,
                                                     const float* __restrict__ PT,
                                                     float* __restrict__ C) {
    extern __shared__ float smem[];
    float* As = smem;
    float* Bs = smem + 128 * AP_LD;

    const int b = blockIdx.y, s0 = blockIdx.x * 128;
    const float* Ab = A + ((size_t)b << 20) + (size_t)s0 * SEQ;
    const float* PTb = PT + (size_t)b * NPAD * SEQ;
    const int tid = threadIdx.x;
    const int warp = tid >> 5, lane = tid & 31;
    const int gid = lane >> 2, tig = lane & 3;
    const int m0 = (warp & 3) * 32;
    const int n0 = (warp >> 2) * 112;

    float c[2][14][4];
#pragma unroll
    for (int mt = 0; mt < 2; mt++)
#pragma unroll
        for (int nt = 0; nt < 14; nt++)
#pragma unroll
            for (int q = 0; q < 4; q++) c[mt][nt][q] = 0.f;

    for (int ch = 0; ch < 16; ch++) {
        const int k0 = ch * AP_BK;
        for (int idx = tid; idx < 128 * 16; idx += 256) {
            int row = idx >> 4, c4 = idx & 15;
            ((float4*)(As + row * AP_LD))[c4] =
                ((const float4*)(Ab + (size_t)row * SEQ + k0))[c4];
        }
        for (int idx = tid; idx < 224 * 16; idx += 256) {
            int row = idx >> 4, c4 = idx & 15;
            ((float4*)(Bs + row * AP_LD))[c4] =
                ((const float4*)(PTb + (size_t)row * SEQ + k0))[c4];
        }
        __syncthreads();

#pragma unroll
        for (int ks = 0; ks < 8; ks++) {
            const int k = ks * 8;
            uint32_t a[2][4];
#pragma unroll
            for (int mt = 0; mt < 2; mt++) {
                const float* ar = As + (m0 + mt * 16 + gid) * AP_LD + k + tig;
                a[mt][0] = __float_as_uint(ar[0]);
                a[mt][1] = __float_as_uint(ar[8 * AP_LD]);
                a[mt][2] = __float_as_uint(ar[4]);
                a[mt][3] = __float_as_uint(ar[8 * AP_LD + 4]);
            }
#pragma unroll
            for (int nt = 0; nt < 14; nt++) {
                const float* br = Bs + (n0 + nt * 8 + gid) * AP_LD + k + tig;
                uint32_t bfr[2];
                bfr[0] = __float_as_uint(br[0]);
                bfr[1] = __float_as_uint(br[4]);
                mma_tf32(c[0][nt], a[0], bfr);
                mma_tf32(c[1][nt], a[1], bfr);
            }
        }
        __syncthreads();
    }

    float* Cb = C + ((size_t)b * SEQ + s0) * DIM;
#pragma unroll
    for (int mt = 0; mt < 2; mt++) {
        int r0 = m0 + mt * 16 + gid;
#pragma unroll
        for (int nt = 0; nt < 14; nt++) {
            int col = n0 + nt * 8 + 2 * tig;
            if (col < DIM) {
                *(float2*)(Cb + (size_t)r0 * DIM + col)       = make_float2(c[mt][nt][0], c[mt][nt][1]);
                *(float2*)(Cb + (size_t)(r0 + 8) * DIM + col) = make_float2(c[mt][nt][2], c[mt][nt][3]);
            }
        }
    }
}

// ================= softmax (scale folded, output tf32-rounded) =================
__global__ void __launch_bounds__(128) softmax_kernel(float* __restrict__ A) {
    const size_t row = blockIdx.x;
    float4* p = (float4*)(A + row * SEQ);
    const int tid = threadIdx.x;
    const int lane = tid & 31, wid = tid >> 5;
    float4 v0 = p[tid];
    float4 v1 = p[tid + 128];

    float mx = fmaxf(fmaxf(fmaxf(v0.x, v0.y), fmaxf(v0.z, v0.w)),
                     fmaxf(fmaxf(v1.x, v1.y), fmaxf(v1.z, v1.w)));
#pragma unroll
    for (int o = 16; o; o >>= 1) mx = fmaxf(mx, __shfl_xor_sync(0xffffffffu, mx, o));
    __shared__ float smx[4], ssm[4];
    if (!lane) smx[wid] = mx;
    __syncthreads();
    float rmax = fmaxf(fmaxf(smx[0], smx[1]), fmaxf(smx[2], smx[3]));

    const float inv = 0.07071067811865475f; // 1/sqrt(200)
    v0.x = __expf((v0.x - rmax) * inv); v0.y = __expf((v0.y - rmax) * inv);
    v0.z = __expf((v0.z - rmax) * inv); v0.w = __expf((v0.w - rmax) * inv);
    v1.x = __expf((v1.x - rmax) * inv); v1.y = __expf((v1.y - rmax) * inv);
    v1.z = __expf((v1.z - rmax) * inv); v1.w = __expf((v1.w - rmax) * inv);
    float s = (v0.x + v0.y) + (v0.z + v0.w) + (v1.x + v1.y) + (v1.z + v1.w);
#pragma unroll
    for (int o = 16; o; o >>= 1) s += __shfl_xor_sync(0xffffffffu, s, o);
    if (!lane) ssm[wid] = s;
    __syncthreads();
    float dinv = 1.0f / (ssm[0] + ssm[1] + ssm[2] + ssm[3]);

    v0.x = tf32r(v0.x * dinv); v0.y = tf32r(v0.y * dinv);
    v0.z = tf32r(v0.z * dinv); v0.w = tf32r(v0.w * dinv);
    v1.x = tf32r(v1.x * dinv); v1.y = tf32r(v1.y * dinv);
    v1.z = tf32r(v1.z * dinv); v1.w = tf32r(v1.w * dinv);
    p[tid] = v0; p[tid + 128] = v1;
}

// ================= ln2d stats =================
__global__ void __launch_bounds__(512) ln_stats_kernel(const float* __restrict__ t,
                                                       float* __restrict__ stats) {
    const int b = blockIdx.x;
    const float4* p = (const float4*)(t + (size_t)b * SEQ * DIM);
    const int N4 = SEQ * DIM / 4;
    const int tid = threadIdx.x;
    const int lane = tid & 31, wid = tid >> 5;
    float s = 0.f, s2 = 0.f;
    for (int i = tid; i < N4; i += 512) {
        float4 v = p[i];
        s  += (v.x + v.y) + (v.z + v.w);
        s2 += v.x * v.x + v.y * v.y + v.z * v.z + v.w * v.w;
    }
#pragma unroll
    for (int o = 16; o; o >>= 1) {
        s  += __shfl_xor_sync(0xffffffffu, s, o);
        s2 += __shfl_xor_sync(0xffffffffu, s2, o);
    }
    __shared__ float sh[16], sh2[16];
    if (!lane) { sh[wid] = s; sh2[wid] = s2; }
    __syncthreads();
    if (tid == 0) {
        float S = 0.f, S2 = 0.f;
#pragma unroll
        for (int i = 0; i < 16; i++) { S += sh[i]; S2 += sh2[i]; }
        const float n = (float)(SEQ * DIM);
        float mean = S / n;
        float var  = S2 / n - mean * mean;
        stats[2 * b]     = mean;
        stats[2 * b + 1] = rsqrtf(var + LN_EPS);
    }
}

__global__ void final_kernel(const float* __restrict__ t, const float* __restrict__ stats,
                             const float* __restrict__ Wd, const float* __restrict__ bd,
                             float* __restrict__ out) {
    int b = blockIdx.x;
    int c = threadIdx.x;
    float m = stats[2 * b], rs = stats[2 * b + 1];
    const float* row = t + ((size_t)b * SEQ + (SEQ - 1)) * DIM;
    if (c < NCLS) {
        float acc = bd[c];
        for (int d = 0; d < DIM; d++)
            acc += (row[d] - m) * rs * Wd[d * NCLS + c];
        out[b * NCLS + c] = acc;
    }
}

// ================= host launcher =================
extern "C" void kernel_launch(void* const* d_in, const int* in_sizes, int n_in,
                              void* d_out, int out_size) {
    (void)in_sizes; (void)n_in; (void)out_size;
    const int*   x    = (const int*)  d_in[0];
    const float* emb  = (const float*)d_in[1];
    const float* pos  = (const float*)d_in[2];
    const float* Wp   = (const float*)d_in[3];
    const float* bp   = (const float*)d_in[4];
    const float* Wm   = (const float*)d_in[5];
    const float* bm   = (const float*)d_in[6];
    const float* W1   = (const float*)d_in[7];
    const float* b1   = (const float*)d_in[8];
    const float* W2   = (const float*)d_in[9];
    const float* b2   = (const float*)d_in[10];
    const float* Wd   = (const float*)d_in[11];
    const float* bd   = (const float*)d_in[12];
    float* out = (float*)d_out;

    float *h_, *t_, *p_, *c_, *PT_, *A_, *WT_, *st_;
    cudaGetSymbolAddress((void**)&h_,  g_h);
    cudaGetSymbolAddress((void**)&t_,  g_t);
    cudaGetSymbolAddress((void**)&p_,  g_p);
    cudaGetSymbolAddress((void**)&c_,  g_c);
    cudaGetSymbolAddress((void**)&PT_, g_PT);
    cudaGetSymbolAddress((void**)&A_,  g_A);
    cudaGetSymbolAddress((void**)&WT_, g_WT);
    cudaGetSymbolAddress((void**)&st_, g_stats);

    const float* WpT = WT_;
    const float* WeT = WT_ + 1 * NPAD * DIM;
    const float* W1T = WT_ + 2 * NPAD * DIM;
    const float* W2T = WT_ + 3 * NPAD * DIM;
    float* st1 = st_;
    float* st2 = st_ + 2 * BATCH;

    const int SM_LG = (128 + 224) * LG_LD * 4;   // 61952
    const int SM_SC = 2 * 128 * SC_LD * 4;       // 208896
    const int SM_AP = (128 + 224) * AP_LD * 4;   // 95744

    // instantiations: RELU, ADDRES, TF32OUT, ALN, RESLN, TERMS
    auto L_proj0 = lgemm_kernel<false, false, true,  false, false, 1>;
    auto L_proj1 = lgemm_kernel<false, false, true,  true,  false, 1>;
    auto L_wm0   = lgemm_kernel<false, true,  false, false, false, 3>;
    auto L_res3  = lgemm_kernel<false, true,  false, false, true,  3>;
    auto L_w1    = lgemm_kernel<true,  false, false, true,  false, 1>;
    cudaFuncSetAttribute(L_proj0, cudaFuncAttributeMaxDynamicSharedMemorySize, SM_LG);
    cudaFuncSetAttribute(L_proj1, cudaFuncAttributeMaxDynamicSharedMemorySize, SM_LG);
    cudaFuncSetAttribute(L_wm0,   cudaFuncAttributeMaxDynamicSharedMemorySize, SM_LG);
    cudaFuncSetAttribute(L_res3,  cudaFuncAttributeMaxDynamicSharedMemorySize, SM_LG);
    cudaFuncSetAttribute(L_w1,    cudaFuncAttributeMaxDynamicSharedMemorySize, SM_LG);
    cudaFuncSetAttribute(scores_mma_kernel, cudaFuncAttributeMaxDynamicSharedMemorySize, SM_SC);
    cudaFuncSetAttribute(ap_mma_kernel,     cudaFuncAttributeMaxDynamicSharedMemorySize, SM_AP);

    const int LGRID = BATCH * SEQ / 128;             // 512
    const int ELT4  = BATCH * SEQ * DIM / 4;

    wprep_kernel<<<dim3((NPAD * DIM + 255) / 256, 4), 256>>>(Wp, Wm, W1, W2, WT_);
    embed_kernel<<<(ELT4 + 255) / 256, 256>>>(x, (const float4*)emb, (const float4*)pos, (float4*)h_);

    for (int st = 0; st < 2; st++) {
        // p = tf32(lnA?(h) @ Wp + bp)
        if (st == 0)
            L_proj0<<<LGRID, 256, SM_LG>>>(h_, WpT, bp, nullptr, nullptr, nullptr, p_);
        else
            L_proj1<<<LGRID, 256, SM_LG>>>(h_, WpT, bp, nullptr, st2, nullptr, p_);
        // PT[b][d][t]
        transpose_kernel<<<dim3(SEQ / 32, 7, BATCH), dim3(32, 8)>>>(p_, PT_);
        // A = P P^T ; softmax ; c = A @ P
        scores_mma_kernel<<<dim3(SEQ / 128, SEQ / 128, BATCH), 256, SM_SC>>>(p_, A_);
        softmax_kernel<<<BATCH * SEQ, 128>>>(A_);
        ap_mma_kernel<<<dim3(SEQ / 128, BATCH), 256, SM_AP>>>(A_, PT_, c_);
        // t = c @ WmEff + bm + lnR?(h)   (3xTF32 trunk)
        if (st == 0)
            L_wm0<<<LGRID, 256, SM_LG>>>(c_, WeT, bm, h_, nullptr, nullptr, t_);
        else
            L_res3<<<LGRID, 256, SM_LG>>>(c_, WeT, bm, h_, nullptr, st2, t_);
        ln_stats_kernel<<<BATCH, 512>>>(t_, st1);
        // ff1 = relu(ln(t) @ W1 + b1)
        L_w1<<<LGRID, 256, SM_LG>>>(t_, W1T, b1, nullptr, st1, nullptr, c_);
        // t2 = ff1 @ W2 + b2 + ln(t)   (3xTF32 trunk) -> h_
        L_res3<<<LGRID, 256, SM_LG>>>(c_, W2T, b2, t_, nullptr, st1, h_);
        ln_stats_kernel<<<BATCH, 512>>>(h_, st2);
    }
    final_kernel<<<BATCH, 32>>>(h_, st2, Wd, bd, out);
}

// round 7
// speedup vs baseline: 2.9927x; 1.4352x over previous
#include <cuda_runtime.h>
#include <cuda_fp16.h>
#include <cuda_bf16.h>
#include <math.h>
#include <stdint.h>

#define BATCH 64
#define SEQ   1024
#define DIM   200
#define NCLS  31
#define NHEAD 8
#define LN_EPS 1e-5f
#define NPAD  224          /* padded N for B operands */
#define PHS   208          /* Ph row stride in halves */

// ---------------- scratch (static device memory; no allocations) ----------------
static __device__ float g_h [BATCH * SEQ * DIM];             // embed / t2 (trunk)
static __device__ float g_t [BATCH * SEQ * DIM];             // pre-LN mid trunk
static __device__ float g_c [BATCH * SEQ * DIM];             // attn out / ff1
static __device__ half  g_Ph[(size_t)BATCH * SEQ * PHS];     // fp16 projection [b][t][208]
static __device__ half  g_PTh[(size_t)BATCH * NPAD * SEQ];   // fp16 transposed proj [b][d][t]
static __device__ half  g_Ah[(size_t)BATCH * SEQ * SEQ];     // fp16 unnormalized exp scores
static __device__ float g_Z [BATCH * SEQ];                   // softmax denominators
static __device__ float g_WT[4 * NPAD * DIM];                // transposed weights [n][k]
static __device__ float g_stats[4 * BATCH];

// ================= helpers =================
__device__ __forceinline__ float tf32r(float x) {
    uint32_t r;
    asm("cvt.rna.tf32.f32 %0, %1;" : "=r"(r) : "f"(x));
    return __uint_as_float(r);
}
__device__ __forceinline__ void mma_tf32(float c[4], const uint32_t a[4], const uint32_t b[2]) {
    asm volatile(
        "mma.sync.aligned.m16n8k8.row.col.f32.tf32.tf32.f32 "
        "{%0,%1,%2,%3}, {%4,%5,%6,%7}, {%8,%9}, {%0,%1,%2,%3};"
        : "+f"(c[0]), "+f"(c[1]), "+f"(c[2]), "+f"(c[3])
        : "r"(a[0]), "r"(a[1]), "r"(a[2]), "r"(a[3]), "r"(b[0]), "r"(b[1]));
}
__device__ __forceinline__ void mma_f16(float c[4], const uint32_t a[4], const uint32_t b[2]) {
    asm volatile(
        "mma.sync.aligned.m16n8k16.row.col.f32.f16.f16.f32 "
        "{%0,%1,%2,%3}, {%4,%5,%6,%7}, {%8,%9}, {%0,%1,%2,%3};"
        : "+f"(c[0]), "+f"(c[1]), "+f"(c[2]), "+f"(c[3])
        : "r"(a[0]), "r"(a[1]), "r"(a[2]), "r"(a[3]), "r"(b[0]), "r"(b[1]));
}

// ================= small kernels =================
__global__ void wprep_kernel(const float* __restrict__ Wp, const float* __restrict__ Wm,
                             const float* __restrict__ W1, const float* __restrict__ W2,
                             float* __restrict__ WT) {
    int i = blockIdx.x * blockDim.x + threadIdx.x;
    if (i >= NPAD * DIM) return;
    int n = i / DIM, k = i % DIM;
    int which = blockIdx.y;
    float v = 0.f;
    if (n < DIM) {
        if (which == 0) v = Wp[k * DIM + n];
        else if (which == 1) {
#pragma unroll
            for (int h = 0; h < NHEAD; h++) v += Wm[(h * DIM + k) * DIM + n];
        } else if (which == 2) v = W1[k * DIM + n];
        else v = W2[k * DIM + n];
    }
    WT[which * NPAD * DIM + i] = v;
}

__global__ void embed_kernel(const int* __restrict__ x, const float4* __restrict__ emb,
                             const float4* __restrict__ pos, float4* __restrict__ h) {
    int g = blockIdx.x * blockDim.x + threadIdx.x;
    const int Q = DIM / 4;
    if (g >= BATCH * SEQ * Q) return;
    int q = g % Q;
    int r = g / Q;
    int s = r % SEQ;
    int tok = x[r];
    float4 e = emb[(size_t)tok * Q + q];
    float4 p = pos[(size_t)s * Q + q];
    h[g] = make_float4(e.x + p.x, e.y + p.y, e.z + p.z, e.w + p.w);
}

__global__ void zeroZ_kernel(float* __restrict__ Z) {
    Z[blockIdx.x * 256 + threadIdx.x] = 0.f;
}

// transpose Ph[b][t][208] -> PTh[b][d][t]  (rows d>=200 get zeros from Ph pad / guard)
__global__ void transpose_h_kernel(const half* __restrict__ Ph, half* __restrict__ PTh) {
    __shared__ half tile[32][33];
    int b = blockIdx.z, t0 = blockIdx.x * 32, d0 = blockIdx.y * 32;
    int tx = threadIdx.x, ty = threadIdx.y;
    const half* src = Ph + ((size_t)b * SEQ + t0) * PHS;
    const half hz = __ushort_as_half((unsigned short)0);
#pragma unroll
    for (int k = 0; k < 4; k++) {
        int r = ty + 8 * k;
        int d = d0 + tx;
        tile[r][tx] = (d < PHS) ? src[r * PHS + d] : hz;
    }
    __syncthreads();
    half* dst = PTh + (size_t)b * NPAD * SEQ;
#pragma unroll
    for (int k = 0; k < 4; k++) {
        int d = d0 + ty + 8 * k;
        dst[(size_t)d * SEQ + t0 + tx] = tile[tx][ty + 8 * k];
    }
}

// ============ layer GEMM (tf32 mma): Y = op( lnA(X) @ W + bias [+ lnR(res)] ) ============
#define LG_LD 44

template <bool RELU, bool ADDRES, bool HOUT, bool ALN, bool RESLN, int TERMS>
__global__ void __launch_bounds__(256) lgemm_kernel(
    const float* __restrict__ X,
    const float* __restrict__ WT,
    const float* __restrict__ bias,
    const float* __restrict__ res,
    const float* __restrict__ statsA,
    const float* __restrict__ statsR,
    float* __restrict__ Y,
    half*  __restrict__ Yh)
{
    extern __shared__ float smem[];
    float* As = smem;                  // [128][44]
    float* Bs = smem + 128 * LG_LD;    // [224][44]

    const int row0 = blockIdx.x * 128;
    const int b = blockIdx.x >> 3;
    const float4* X4 = (const float4*)(X + (size_t)row0 * DIM);
    const float4* W4 = (const float4*)WT;
    const int tid = threadIdx.x;
    const int warp = tid >> 5, lane = tid & 31;
    const int gid = lane >> 2, tig = lane & 3;
    const int m0 = (warp & 3) * 32;
    const int n0 = (warp >> 2) * 112;

    float mA = 0.f, rA = 1.f;
    if (ALN) { mA = statsA[2 * b]; rA = statsA[2 * b + 1]; }

    float c[2][14][4];
#pragma unroll
    for (int mt = 0; mt < 2; mt++)
#pragma unroll
        for (int nt = 0; nt < 14; nt++)
#pragma unroll
            for (int q = 0; q < 4; q++) c[mt][nt][q] = 0.f;

#pragma unroll
    for (int ch = 0; ch < 5; ch++) {
        const int k0 = ch * 40;
#pragma unroll
        for (int it = 0; it < 5; it++) {
            int idx = tid + it * 256;
            int row = idx / 10, c4 = idx % 10;
            float4 v = X4[(size_t)row * 50 + (k0 >> 2) + c4];
            if (ALN) {
                v.x = (v.x - mA) * rA; v.y = (v.y - mA) * rA;
                v.z = (v.z - mA) * rA; v.w = (v.w - mA) * rA;
            }
            *(float4*)(As + row * LG_LD + c4 * 4) = v;
        }
        for (int idx = tid; idx < 224 * 10; idx += 256) {
            int row = idx / 10, c4 = idx % 10;
            *(float4*)(Bs + row * LG_LD + c4 * 4) = W4[(size_t)row * 50 + (k0 >> 2) + c4];
        }
        __syncthreads();

#pragma unroll
        for (int ks = 0; ks < 5; ks++) {
            const int k = ks * 8;
            uint32_t ahi[2][4], alo[2][4];
#pragma unroll
            for (int mt = 0; mt < 2; mt++) {
                const float* ar = As + (m0 + mt * 16 + gid) * LG_LD + k + tig;
                float a0 = ar[0], a1 = ar[8 * LG_LD], a2 = ar[4], a3 = ar[8 * LG_LD + 4];
                float h0 = tf32r(a0), h1 = tf32r(a1), h2 = tf32r(a2), h3 = tf32r(a3);
                ahi[mt][0] = __float_as_uint(h0); ahi[mt][1] = __float_as_uint(h1);
                ahi[mt][2] = __float_as_uint(h2); ahi[mt][3] = __float_as_uint(h3);
                if (TERMS == 3) {
                    alo[mt][0] = __float_as_uint(a0 - h0);
                    alo[mt][1] = __float_as_uint(a1 - h1);
                    alo[mt][2] = __float_as_uint(a2 - h2);
                    alo[mt][3] = __float_as_uint(a3 - h3);
                }
            }
#pragma unroll
            for (int nt = 0; nt < 14; nt++) {
                const float* br = Bs + (n0 + nt * 8 + gid) * LG_LD + k + tig;
                float b0 = br[0], b1 = br[4];
                float bh0 = tf32r(b0), bh1 = tf32r(b1);
                uint32_t bhi[2] = { __float_as_uint(bh0), __float_as_uint(bh1) };
                if (TERMS == 3) {
                    uint32_t blo[2] = { __float_as_uint(b0 - bh0), __float_as_uint(b1 - bh1) };
#pragma unroll
                    for (int mt = 0; mt < 2; mt++) {
                        mma_tf32(c[mt][nt], ahi[mt], blo);
                        mma_tf32(c[mt][nt], alo[mt], bhi);
                        mma_tf32(c[mt][nt], ahi[mt], bhi);
                    }
                } else {
#pragma unroll
                    for (int mt = 0; mt < 2; mt++) mma_tf32(c[mt][nt], ahi[mt], bhi);
                }
            }
        }
        __syncthreads();
    }

    float mR = 0.f, rR = 1.f;
    if (RESLN) { mR = statsR[2 * b]; rR = statsR[2 * b + 1]; }

    float* Yb = Y ? (Y + (size_t)row0 * DIM) : (float*)0;
    half*  Yhb = HOUT ? (Yh + (size_t)row0 * PHS) : (half*)0;
    const float* Rb = ADDRES ? (res + (size_t)row0 * DIM) : (const float*)0;
#pragma unroll
    for (int mt = 0; mt < 2; mt++) {
        int r0 = m0 + mt * 16 + gid;
#pragma unroll
        for (int nt = 0; nt < 14; nt++) {
            int col = n0 + nt * 8 + 2 * tig;
            if (col < DIM) {
                float bx = bias[col], by = bias[col + 1];
                float v0 = c[mt][nt][0] + bx, v1 = c[mt][nt][1] + by;
                float v2 = c[mt][nt][2] + bx, v3 = c[mt][nt][3] + by;
                if (ADDRES) {
                    float q0 = Rb[(size_t)r0 * DIM + col],       q1 = Rb[(size_t)r0 * DIM + col + 1];
                    float q2 = Rb[(size_t)(r0 + 8) * DIM + col], q3 = Rb[(size_t)(r0 + 8) * DIM + col + 1];
                    if (RESLN) {
                        q0 = (q0 - mR) * rR; q1 = (q1 - mR) * rR;
                        q2 = (q2 - mR) * rR; q3 = (q3 - mR) * rR;
                    }
                    v0 += q0; v1 += q1; v2 += q2; v3 += q3;
                }
                if (RELU) {
                    v0 = fmaxf(v0, 0.f); v1 = fmaxf(v1, 0.f);
                    v2 = fmaxf(v2, 0.f); v3 = fmaxf(v3, 0.f);
                }
                if (HOUT) {
                    *(__half2*)(Yhb + (size_t)r0 * PHS + col)       = __floats2half2_rn(v0, v1);
                    *(__half2*)(Yhb + (size_t)(r0 + 8) * PHS + col) = __floats2half2_rn(v2, v3);
                } else {
                    *(float2*)(Yb + (size_t)r0 * DIM + col)       = make_float2(v0, v1);
                    *(float2*)(Yb + (size_t)(r0 + 8) * DIM + col) = make_float2(v2, v3);
                }
            } else if (HOUT && col < PHS) {
                __half2 z = __floats2half2_rn(0.f, 0.f);
                *(__half2*)(Yhb + (size_t)r0 * PHS + col)       = z;
                *(__half2*)(Yhb + (size_t)(r0 + 8) * PHS + col) = z;
            }
        }
    }
}

// ===== fp16 scores + fused exp + row-sum atomics: E[b] = exp(P P^T / sqrt(200) - 8) =====
// tile 128x128, K padded to 208 halves. smem stride 216 halves (h2 108 == 12 mod 32).
__global__ void __launch_bounds__(256) scores_h_kernel(const half* __restrict__ Ph,
                                                       half* __restrict__ Ah,
                                                       float* __restrict__ Z) {
    extern __shared__ half smh[];
    half* Qs = smh;               // [128][216]
    half* Ks = smh + 128 * 216;   // [128][216]

    const int b = blockIdx.z, s0 = blockIdx.y * 128, t0 = blockIdx.x * 128;
    const int tid = threadIdx.x;
    const float4* Pq = (const float4*)(Ph + ((size_t)b * SEQ + s0) * PHS);
    const float4* Pk = (const float4*)(Ph + ((size_t)b * SEQ + t0) * PHS);

    for (int idx = tid; idx < 128 * 26; idx += 256) {
        int row = idx / 26, c4 = idx % 26;
        ((float4*)Qs)[row * 27 + c4] = Pq[row * 26 + c4];
        ((float4*)Ks)[row * 27 + c4] = Pk[row * 26 + c4];
    }
    __syncthreads();

    const int warp = tid >> 5, lane = tid & 31;
    const int gid = lane >> 2, tig = lane & 3;
    const int m0 = (warp & 3) * 32;
    const int n0 = (warp >> 2) * 64;

    float c[2][8][4];
#pragma unroll
    for (int mt = 0; mt < 2; mt++)
#pragma unroll
        for (int nt = 0; nt < 8; nt++)
#pragma unroll
            for (int q = 0; q < 4; q++) c[mt][nt][q] = 0.f;

    const uint32_t* Qh2 = (const uint32_t*)Qs;
    const uint32_t* Kh2 = (const uint32_t*)Ks;
#pragma unroll
    for (int ks = 0; ks < 13; ks++) {
        uint32_t a[2][4];
#pragma unroll
        for (int mt = 0; mt < 2; mt++) {
            const uint32_t* qr = Qh2 + (m0 + mt * 16 + gid) * 108 + ks * 8 + tig;
            a[mt][0] = qr[0];
            a[mt][1] = qr[8 * 108];
            a[mt][2] = qr[4];
            a[mt][3] = qr[8 * 108 + 4];
        }
#pragma unroll
        for (int nt = 0; nt < 8; nt++) {
            const uint32_t* kr = Kh2 + (n0 + nt * 8 + gid) * 108 + ks * 8 + tig;
            uint32_t bf[2] = { kr[0], kr[4] };
            mma_f16(c[0][nt], a[0], bf);
            mma_f16(c[1][nt], a[1], bf);
        }
    }

    // epilogue: exp(s*inv - 8), fp16 store, row-sum atomics
    const float inv = 0.07071067811865475f; // 1/sqrt(200)
    half* Ab = Ah + ((size_t)b << 20);
    float rs[2][2] = {{0.f, 0.f}, {0.f, 0.f}};
#pragma unroll
    for (int mt = 0; mt < 2; mt++) {
        int r0 = s0 + m0 + mt * 16 + gid;
#pragma unroll
        for (int nt = 0; nt < 8; nt++) {
            int col = t0 + n0 + nt * 8 + 2 * tig;
            float e0 = __expf(fmaf(c[mt][nt][0], inv, -8.f));
            float e1 = __expf(fmaf(c[mt][nt][1], inv, -8.f));
            float e2 = __expf(fmaf(c[mt][nt][2], inv, -8.f));
            float e3 = __expf(fmaf(c[mt][nt][3], inv, -8.f));
            *(__half2*)(Ab + (size_t)r0 * SEQ + col)       = __floats2half2_rn(e0, e1);
            *(__half2*)(Ab + (size_t)(r0 + 8) * SEQ + col) = __floats2half2_rn(e2, e3);
            rs[mt][0] += e0 + e1;
            rs[mt][1] += e2 + e3;
        }
    }
#pragma unroll
    for (int mt = 0; mt < 2; mt++)
#pragma unroll
        for (int hh = 0; hh < 2; hh++) {
            float s = rs[mt][hh];
            s += __shfl_xor_sync(0xffffffffu, s, 1);
            s += __shfl_xor_sync(0xffffffffu, s, 2);
            if (tig == 0)
                atomicAdd(Z + (size_t)b * SEQ + s0 + m0 + mt * 16 + gid + hh * 8, s);
        }
}

// ===== fp16 AP: c[b] = (E[b] @ P[b]) / Z  (tile 128x224, K=1024 in 8 chunks of 128) =====
__global__ void __launch_bounds__(256) ap_h_kernel(const half* __restrict__ Ah,
                                                   const half* __restrict__ PTh,
                                                   const float* __restrict__ Z,
                                                   float* __restrict__ C) {
    extern __shared__ half smh[];
    half* As = smh;               // [128][136]
    half* Bs = smh + 128 * 136;   // [224][136]

    const int b = blockIdx.y, s0 = blockIdx.x * 128;
    const float4* A4 = (const float4*)(Ah + ((size_t)b << 20) + (size_t)s0 * SEQ);
    const float4* B4 = (const float4*)(PTh + (size_t)b * NPAD * SEQ);
    const int tid = threadIdx.x;
    const int warp = tid >> 5, lane = tid & 31;
    const int gid = lane >> 2, tig = lane & 3;
    const int m0 = (warp & 3) * 32;
    const int n0 = (warp >> 2) * 112;

    float c[2][14][4];
#pragma unroll
    for (int mt = 0; mt < 2; mt++)
#pragma unroll
        for (int nt = 0; nt < 14; nt++)
#pragma unroll
            for (int q = 0; q < 4; q++) c[mt][nt][q] = 0.f;

    const uint32_t* Ah2 = (const uint32_t*)As;
    const uint32_t* Bh2 = (const uint32_t*)Bs;

    for (int ch = 0; ch < 8; ch++) {
        for (int idx = tid; idx < 128 * 16; idx += 256) {
            int row = idx >> 4, c4 = idx & 15;
            ((float4*)As)[row * 17 + c4] = A4[row * 128 + ch * 16 + c4];
        }
        for (int idx = tid; idx < 224 * 16; idx += 256) {
            int row = idx >> 4, c4 = idx & 15;
            ((float4*)Bs)[row * 17 + c4] = B4[row * 128 + ch * 16 + c4];
        }
        __syncthreads();

#pragma unroll
        for (int ks = 0; ks < 8; ks++) {
            uint32_t a[2][4];
#pragma unroll
            for (int mt = 0; mt < 2; mt++) {
                const uint32_t* ar = Ah2 + (m0 + mt * 16 + gid) * 68 + ks * 8 + tig;
                a[mt][0] = ar[0];
                a[mt][1] = ar[8 * 68];
                a[mt][2] = ar[4];
                a[mt][3] = ar[8 * 68 + 4];
            }
#pragma unroll
            for (int nt = 0; nt < 14; nt++) {
                const uint32_t* br = Bh2 + (n0 + nt * 8 + gid) * 68 + ks * 8 + tig;
                uint32_t bf[2] = { br[0], br[4] };
                mma_f16(c[0][nt], a[0], bf);
                mma_f16(c[1][nt], a[1], bf);
            }
        }
        __syncthreads();
    }

    float* Cb = C + ((size_t)b * SEQ + s0) * DIM;
#pragma unroll
    for (int mt = 0; mt < 2; mt++) {
        int r0 = m0 + mt * 16 + gid;
        float z0 = 1.f / Z[(size_t)b * SEQ + s0 + r0];
        float z8 = 1.f / Z[(size_t)b * SEQ + s0 + r0 + 8];
#pragma unroll
        for (int nt = 0; nt < 14; nt++) {
            int col = n0 + nt * 8 + 2 * tig;
            if (col < DIM) {
                *(float2*)(Cb + (size_t)r0 * DIM + col) =
                    make_float2(c[mt][nt][0] * z0, c[mt][nt][1] * z0);
                *(float2*)(Cb + (size_t)(r0 + 8) * DIM + col) =
                    make_float2(c[mt][nt][2] * z8, c[mt][nt][3] * z8);
            }
        }
    }
}

// ================= ln2d stats =================
__global__ void __launch_bounds__(512) ln_stats_kernel(const float* __restrict__ t,
                                                       float* __restrict__ stats) {
    const int b = blockIdx.x;
    const float4* p = (const float4*)(t + (size_t)b * SEQ * DIM);
    const int N4 = SEQ * DIM / 4;
    const int tid = threadIdx.x;
    const int lane = tid & 31, wid = tid >> 5;
    float s = 0.f, s2 = 0.f;
    for (int i = tid; i < N4; i += 512) {
        float4 v = p[i];
        s  += (v.x + v.y) + (v.z + v.w);
        s2 += v.x * v.x + v.y * v.y + v.z * v.z + v.w * v.w;
    }
#pragma unroll
    for (int o = 16; o; o >>= 1) {
        s  += __shfl_xor_sync(0xffffffffu, s, o);
        s2 += __shfl_xor_sync(0xffffffffu, s2, o);
    }
    __shared__ float sh[16], sh2[16];
    if (!lane) { sh[wid] = s; sh2[wid] = s2; }
    __syncthreads();
    if (tid == 0) {
        float S = 0.f, S2 = 0.f;
#pragma unroll
        for (int i = 0; i < 16; i++) { S += sh[i]; S2 += sh2[i]; }
        const float n = (float)(SEQ * DIM);
        float mean = S / n;
        float var  = S2 / n - mean * mean;
        stats[2 * b]     = mean;
        stats[2 * b + 1] = rsqrtf(var + LN_EPS);
    }
}

__global__ void final_kernel(const float* __restrict__ t, const float* __restrict__ stats,
                             const float* __restrict__ Wd, const float* __restrict__ bd,
                             float* __restrict__ out) {
    int b = blockIdx.x;
    int c = threadIdx.x;
    float m = stats[2 * b], rs = stats[2 * b + 1];
    const float* row = t + ((size_t)b * SEQ + (SEQ - 1)) * DIM;
    if (c < NCLS) {
        float acc = bd[c];
        for (int d = 0; d < DIM; d++)
            acc += (row[d] - m) * rs * Wd[d * NCLS + c];
        out[b * NCLS + c] = acc;
    }
}

// ================= host launcher =================
extern "C" void kernel_launch(void* const* d_in, const int* in_sizes, int n_in,
                              void* d_out, int out_size) {
    (void)in_sizes; (void)n_in; (void)out_size;
    const int*   x    = (const int*)  d_in[0];
    const float* emb  = (const float*)d_in[1];
    const float* pos  = (const float*)d_in[2];
    const float* Wp   = (const float*)d_in[3];
    const float* bp   = (const float*)d_in[4];
    const float* Wm   = (const float*)d_in[5];
    const float* bm   = (const float*)d_in[6];
    const float* W1   = (const float*)d_in[7];
    const float* b1   = (const float*)d_in[8];
    const float* W2   = (const float*)d_in[9];
    const float* b2   = (const float*)d_in[10];
    const float* Wd   = (const float*)d_in[11];
    const float* bd   = (const float*)d_in[12];
    float* out = (float*)d_out;

    float *h_, *t_, *c_, *Z_, *WT_, *st_;
    half *Ph_, *PTh_, *Ah_;
    cudaGetSymbolAddress((void**)&h_,   g_h);
    cudaGetSymbolAddress((void**)&t_,   g_t);
    cudaGetSymbolAddress((void**)&c_,   g_c);
    cudaGetSymbolAddress((void**)&Ph_,  g_Ph);
    cudaGetSymbolAddress((void**)&PTh_, g_PTh);
    cudaGetSymbolAddress((void**)&Ah_,  g_Ah);
    cudaGetSymbolAddress((void**)&Z_,   g_Z);
    cudaGetSymbolAddress((void**)&WT_,  g_WT);
    cudaGetSymbolAddress((void**)&st_,  g_stats);

    const float* WpT = WT_;
    const float* WeT = WT_ + 1 * NPAD * DIM;
    const float* W1T = WT_ + 2 * NPAD * DIM;
    const float* W2T = WT_ + 3 * NPAD * DIM;
    float* st1 = st_;
    float* st2 = st_ + 2 * BATCH;

    const int SM_LG = (128 + 224) * LG_LD * 4;   // 61952
    const int SM_SC = 2 * 128 * 216 * 2;         // 110592
    const int SM_AP = (128 + 224) * 136 * 2;     // 95744

    // RELU, ADDRES, HOUT, ALN, RESLN, TERMS
    auto L_proj0 = lgemm_kernel<false, false, true,  false, false, 1>;
    auto L_proj1 = lgemm_kernel<false, false, true,  true,  false, 1>;
    auto L_wm0   = lgemm_kernel<false, true,  false, false, false, 3>;
    auto L_res3  = lgemm_kernel<false, true,  false, false, true,  3>;
    auto L_w1    = lgemm_kernel<true,  false, false, true,  false, 1>;
    cudaFuncSetAttribute(L_proj0, cudaFuncAttributeMaxDynamicSharedMemorySize, SM_LG);
    cudaFuncSetAttribute(L_proj1, cudaFuncAttributeMaxDynamicSharedMemorySize, SM_LG);
    cudaFuncSetAttribute(L_wm0,   cudaFuncAttributeMaxDynamicSharedMemorySize, SM_LG);
    cudaFuncSetAttribute(L_res3,  cudaFuncAttributeMaxDynamicSharedMemorySize, SM_LG);
    cudaFuncSetAttribute(L_w1,    cudaFuncAttributeMaxDynamicSharedMemorySize, SM_LG);
    cudaFuncSetAttribute(scores_h_kernel, cudaFuncAttributeMaxDynamicSharedMemorySize, SM_SC);
    cudaFuncSetAttribute(ap_h_kernel,     cudaFuncAttributeMaxDynamicSharedMemorySize, SM_AP);

    const int LGRID = BATCH * SEQ / 128;             // 512
    const int ELT4  = BATCH * SEQ * DIM / 4;

    wprep_kernel<<<dim3((NPAD * DIM + 255) / 256, 4), 256>>>(Wp, Wm, W1, W2, WT_);
    embed_kernel<<<(ELT4 + 255) / 256, 256>>>(x, (const float4*)emb, (const float4*)pos, (float4*)h_);

    for (int st = 0; st < 2; st++) {
        // p = fp16(lnA?(h) @ Wp + bp) -> Ph
        if (st == 0)
            L_proj0<<<LGRID, 256, SM_LG>>>(h_, WpT, bp, nullptr, nullptr, nullptr, nullptr, Ph_);
        else
            L_proj1<<<LGRID, 256, SM_LG>>>(h_, WpT, bp, nullptr, st2, nullptr, nullptr, Ph_);
        // PTh[b][d][t]
        transpose_h_kernel<<<dim3(SEQ / 32, 7, BATCH), dim3(32, 8)>>>(Ph_, PTh_);
        // E = exp(P P^T * inv - 8) (fp16), Z row sums
        zeroZ_kernel<<<BATCH * SEQ / 256, 256>>>(Z_);
        scores_h_kernel<<<dim3(SEQ / 128, SEQ / 128, BATCH), 256, SM_SC>>>(Ph_, Ah_, Z_);
        // c = (E @ P) / Z
        ap_h_kernel<<<dim3(SEQ / 128, BATCH), 256, SM_AP>>>(Ah_, PTh_, Z_, c_);
        // t = c @ WmEff + bm + lnR?(h)   (3xTF32 trunk)
        if (st == 0)
            L_wm0<<<LGRID, 256, SM_LG>>>(c_, WeT, bm, h_, nullptr, nullptr, t_, nullptr);
        else
            L_res3<<<LGRID, 256, SM_LG>>>(c_, WeT, bm, h_, nullptr, st2, t_, nullptr);
        ln_stats_kernel<<<BATCH, 512>>>(t_, st1);
        // ff1 = relu(ln(t) @ W1 + b1)
        L_w1<<<LGRID, 256, SM_LG>>>(t_, W1T, b1, nullptr, st1, nullptr, c_, nullptr);
        // t2 = ff1 @ W2 + b2 + ln(t)   (3xTF32 trunk) -> h_
        L_res3<<<LGRID, 256, SM_LG>>>(c_, W2T, b2, t_, nullptr, st1, h_, nullptr);
        ln_stats_kernel<<<BATCH, 512>>>(h_, st2);
    }
    final_kernel<<<BATCH, 32>>>(h_, st2, Wd, bd, out);
}

// round 9
// speedup vs baseline: 3.4521x; 1.1535x over previous
#include <cuda_runtime.h>
#include <cuda_fp16.h>
#include <cuda_bf16.h>
#include <math.h>
#include <stdint.h>

#define BATCH 64
#define SEQ   1024
#define DIM   200
#define NCLS  31
#define NHEAD 8
#define LN_EPS 1e-5f
#define NPAD  224
#define PHS   208          /* Ph row stride in halves (416 B) */

// ---------------- scratch (static device memory; no allocations) ----------------
static __device__ float g_h [BATCH * SEQ * DIM];
static __device__ float g_t [BATCH * SEQ * DIM];
static __device__ float g_c [BATCH * SEQ * DIM];
static __device__ half  g_Ph[(size_t)BATCH * SEQ * PHS];
static __device__ half  g_PTh[(size_t)BATCH * NPAD * SEQ];
static __device__ float g_WT[4 * NPAD * DIM];
static __device__ float g_stats[4 * BATCH];
static __device__ float g_acc[4 * BATCH];     // ln sum/sumsq accumulators (BSS zero; finalize resets)

extern __shared__ char dyn_smem[];

// ================= helpers =================
__device__ __forceinline__ float tf32r(float x) {
    uint32_t r;
    asm("cvt.rna.tf32.f32 %0, %1;" : "=r"(r) : "f"(x));
    return __uint_as_float(r);
}
__device__ __forceinline__ void mma_tf32(float c[4], const uint32_t a[4], const uint32_t b[2]) {
    asm volatile(
        "mma.sync.aligned.m16n8k8.row.col.f32.tf32.tf32.f32 "
        "{%0,%1,%2,%3}, {%4,%5,%6,%7}, {%8,%9}, {%0,%1,%2,%3};"
        : "+f"(c[0]), "+f"(c[1]), "+f"(c[2]), "+f"(c[3])
        : "r"(a[0]), "r"(a[1]), "r"(a[2]), "r"(a[3]), "r"(b[0]), "r"(b[1]));
}
__device__ __forceinline__ void mma_f16(float c[4], const uint32_t a[4], const uint32_t b[2]) {
    asm volatile(
        "mma.sync.aligned.m16n8k16.row.col.f32.f16.f16.f32 "
        "{%0,%1,%2,%3}, {%4,%5,%6,%7}, {%8,%9}, {%0,%1,%2,%3};"
        : "+f"(c[0]), "+f"(c[1]), "+f"(c[2]), "+f"(c[3])
        : "r"(a[0]), "r"(a[1]), "r"(a[2]), "r"(a[3]), "r"(b[0]), "r"(b[1]));
}
__device__ __forceinline__ uint32_t smem_u32(const void* p) {
    uint32_t a;
    asm("{ .reg .u64 t; cvta.to.shared.u64 t, %1; cvt.u32.u64 %0, t; }" : "=r"(a) : "l"(p));
    return a;
}
__device__ __forceinline__ void cp16(uint32_t dst, const void* src) {
    asm volatile("cp.async.cg.shared.global [%0], [%1], 16;" :: "r"(dst), "l"(src));
}
#define CP_COMMIT() asm volatile("cp.async.commit_group;" ::: "memory")
#define CP_WAIT0()  asm volatile("cp.async.wait_group 0;" ::: "memory")
__device__ __forceinline__ uint32_t pack_h2(float a, float b) {
    __half2 h = __floats2half2_rn(a, b);
    return *(uint32_t*)&h;
}

// ================= small kernels =================
__global__ void wprep_kernel(const float* __restrict__ Wp, const float* __restrict__ Wm,
                             const float* __restrict__ W1, const float* __restrict__ W2,
                             float* __restrict__ WT) {
    int i = blockIdx.x * blockDim.x + threadIdx.x;
    if (i >= NPAD * DIM) return;
    int n = i / DIM, k = i % DIM;
    int which = blockIdx.y;
    float v = 0.f;
    if (n < DIM) {
        if (which == 0) v = Wp[k * DIM + n];
        else if (which == 1) {
#pragma unroll
            for (int h = 0; h < NHEAD; h++) v += Wm[(h * DIM + k) * DIM + n];
        } else if (which == 2) v = W1[k * DIM + n];
        else v = W2[k * DIM + n];
    }
    WT[which * NPAD * DIM + i] = v;
}

__global__ void embed_kernel(const int* __restrict__ x, const float4* __restrict__ emb,
                             const float4* __restrict__ pos, float4* __restrict__ h) {
    int g = blockIdx.x * blockDim.x + threadIdx.x;
    const int Q = DIM / 4;
    if (g >= BATCH * SEQ * Q) return;
    int q = g % Q;
    int r = g / Q;
    int s = r % SEQ;
    int tok = x[r];
    float4 e = emb[(size_t)tok * Q + q];
    float4 p = pos[(size_t)s * Q + q];
    h[g] = make_float4(e.x + p.x, e.y + p.y, e.z + p.z, e.w + p.w);
}

// transpose Ph[b][t][208] -> PTh[b][d][t]
__global__ void transpose_h_kernel(const half* __restrict__ Ph, half* __restrict__ PTh) {
    __shared__ half tile[32][33];
    int b = blockIdx.z, t0 = blockIdx.x * 32, d0 = blockIdx.y * 32;
    int tx = threadIdx.x, ty = threadIdx.y;
    const half* src = Ph + ((size_t)b * SEQ + t0) * PHS;
    const half hz = __ushort_as_half((unsigned short)0);
#pragma unroll
    for (int k = 0; k < 4; k++) {
        int r = ty + 8 * k;
        int d = d0 + tx;
        tile[r][tx] = (d < PHS) ? src[r * PHS + d] : hz;
    }
    __syncthreads();
    half* dst = PTh + (size_t)b * NPAD * SEQ;
#pragma unroll
    for (int k = 0; k < 4; k++) {
        int d = d0 + ty + 8 * k;
        dst[(size_t)d * SEQ + t0 + tx] = tile[tx][ty + 8 * k];
    }
}

// finalize ln stats from accumulators; reset accumulators (graph-replay invariant)
__global__ void finalize_kernel(float* __restrict__ acc, float* __restrict__ stats) {
    int b = threadIdx.x;
    if (b < BATCH) {
        float S = acc[2 * b], S2 = acc[2 * b + 1];
        const float n = (float)(SEQ * DIM);
        float mean = S / n;
        float var  = S2 / n - mean * mean;
        stats[2 * b]     = mean;
        stats[2 * b + 1] = rsqrtf(var + LN_EPS);
        acc[2 * b] = 0.f; acc[2 * b + 1] = 0.f;
    }
}

// ============ layer GEMM (tf32 mma): Y = op( lnA(X) @ W + bias [+ lnR(res)] ) ============
#define LG_LD 44

template <bool RELU, bool ADDRES, bool HOUT, bool ALN, bool RESLN, int TERMS, bool SUMOUT>
__global__ void __launch_bounds__(256) lgemm_kernel(
    const float* __restrict__ X,
    const float* __restrict__ WT,
    const float* __restrict__ bias,
    const float* __restrict__ res,
    const float* __restrict__ statsA,
    const float* __restrict__ statsR,
    float* __restrict__ Y,
    half*  __restrict__ Yh,
    float* __restrict__ acc)
{
    float* As = (float*)dyn_smem;                  // [128][44]
    float* Bs = (float*)dyn_smem + 128 * LG_LD;    // [224][44]

    const int row0 = blockIdx.x * 128;
    const int b = blockIdx.x >> 3;
    const float4* X4 = (const float4*)(X + (size_t)row0 * DIM);
    const float4* W4 = (const float4*)WT;
    const int tid = threadIdx.x;
    const int warp = tid >> 5, lane = tid & 31;
    const int gid = lane >> 2, tig = lane & 3;
    const int m0 = (warp & 3) * 32;
    const int n0 = (warp >> 2) * 112;

    float mA = 0.f, rA = 1.f;
    if (ALN) { mA = statsA[2 * b]; rA = statsA[2 * b + 1]; }

    float c[2][14][4];
#pragma unroll
    for (int mt = 0; mt < 2; mt++)
#pragma unroll
        for (int nt = 0; nt < 14; nt++)
#pragma unroll
            for (int q = 0; q < 4; q++) c[mt][nt][q] = 0.f;

#pragma unroll
    for (int ch = 0; ch < 5; ch++) {
        const int k0 = ch * 40;
#pragma unroll
        for (int it = 0; it < 5; it++) {
            int idx = tid + it * 256;
            int row = idx / 10, c4 = idx % 10;
            float4 v = X4[(size_t)row * 50 + (k0 >> 2) + c4];
            if (ALN) {
                v.x = (v.x - mA) * rA; v.y = (v.y - mA) * rA;
                v.z = (v.z - mA) * rA; v.w = (v.w - mA) * rA;
            }
            *(float4*)(As + row * LG_LD + c4 * 4) = v;
        }
        for (int idx = tid; idx < 224 * 10; idx += 256) {
            int row = idx / 10, c4 = idx % 10;
            *(float4*)(Bs + row * LG_LD + c4 * 4) = W4[(size_t)row * 50 + (k0 >> 2) + c4];
        }
        __syncthreads();

#pragma unroll
        for (int ks = 0; ks < 5; ks++) {
            const int k = ks * 8;
            uint32_t ahi[2][4], alo[2][4];
#pragma unroll
            for (int mt = 0; mt < 2; mt++) {
                const float* ar = As + (m0 + mt * 16 + gid) * LG_LD + k + tig;
                float a0 = ar[0], a1 = ar[8 * LG_LD], a2 = ar[4], a3 = ar[8 * LG_LD + 4];
                float h0 = tf32r(a0), h1 = tf32r(a1), h2 = tf32r(a2), h3 = tf32r(a3);
                ahi[mt][0] = __float_as_uint(h0); ahi[mt][1] = __float_as_uint(h1);
                ahi[mt][2] = __float_as_uint(h2); ahi[mt][3] = __float_as_uint(h3);
                if (TERMS == 3) {
                    alo[mt][0] = __float_as_uint(a0 - h0);
                    alo[mt][1] = __float_as_uint(a1 - h1);
                    alo[mt][2] = __float_as_uint(a2 - h2);
                    alo[mt][3] = __float_as_uint(a3 - h3);
                }
            }
#pragma unroll
            for (int nt = 0; nt < 14; nt++) {
                const float* br = Bs + (n0 + nt * 8 + gid) * LG_LD + k + tig;
                float b0 = br[0], b1 = br[4];
                float bh0 = tf32r(b0), bh1 = tf32r(b1);
                uint32_t bhi[2] = { __float_as_uint(bh0), __float_as_uint(bh1) };
                if (TERMS == 3) {
                    uint32_t blo[2] = { __float_as_uint(b0 - bh0), __float_as_uint(b1 - bh1) };
#pragma unroll
                    for (int mt = 0; mt < 2; mt++) {
                        mma_tf32(c[mt][nt], ahi[mt], blo);
                        mma_tf32(c[mt][nt], alo[mt], bhi);
                        mma_tf32(c[mt][nt], ahi[mt], bhi);
                    }
                } else {
#pragma unroll
                    for (int mt = 0; mt < 2; mt++) mma_tf32(c[mt][nt], ahi[mt], bhi);
                }
            }
        }
        __syncthreads();
    }

    float mR = 0.f, rR = 1.f;
    if (RESLN) { mR = statsR[2 * b]; rR = statsR[2 * b + 1]; }

    float* Yb = (!HOUT) ? (Y + (size_t)row0 * DIM) : (float*)0;
    half*  Yhb = HOUT ? (Yh + (size_t)row0 * PHS) : (half*)0;
    const float* Rb = ADDRES ? (res + (size_t)row0 * DIM) : (const float*)0;

    float ssum = 0.f, ssq = 0.f;
#pragma unroll
    for (int mt = 0; mt < 2; mt++) {
        int r0 = m0 + mt * 16 + gid;
#pragma unroll
        for (int nt = 0; nt < 14; nt++) {
            int col = n0 + nt * 8 + 2 * tig;
            if (col < DIM) {
                float bx = bias[col], by = bias[col + 1];
                float v0 = c[mt][nt][0] + bx, v1 = c[mt][nt][1] + by;
                float v2 = c[mt][nt][2] + bx, v3 = c[mt][nt][3] + by;
                if (ADDRES) {
                    float q0 = Rb[(size_t)r0 * DIM + col],       q1 = Rb[(size_t)r0 * DIM + col + 1];
                    float q2 = Rb[(size_t)(r0 + 8) * DIM + col], q3 = Rb[(size_t)(r0 + 8) * DIM + col + 1];
                    if (RESLN) {
                        q0 = (q0 - mR) * rR; q1 = (q1 - mR) * rR;
                        q2 = (q2 - mR) * rR; q3 = (q3 - mR) * rR;
                    }
                    v0 += q0; v1 += q1; v2 += q2; v3 += q3;
                }
                if (RELU) {
                    v0 = fmaxf(v0, 0.f); v1 = fmaxf(v1, 0.f);
                    v2 = fmaxf(v2, 0.f); v3 = fmaxf(v3, 0.f);
                }
                if (SUMOUT) {
                    ssum += (v0 + v1) + (v2 + v3);
                    ssq  += v0 * v0 + v1 * v1 + v2 * v2 + v3 * v3;
                }
                if (HOUT) {
                    *(__half2*)(Yhb + (size_t)r0 * PHS + col)       = __floats2half2_rn(v0, v1);
                    *(__half2*)(Yhb + (size_t)(r0 + 8) * PHS + col) = __floats2half2_rn(v2, v3);
                } else {
                    *(float2*)(Yb + (size_t)r0 * DIM + col)       = make_float2(v0, v1);
                    *(float2*)(Yb + (size_t)(r0 + 8) * DIM + col) = make_float2(v2, v3);
                }
            } else if (HOUT && col < PHS) {
                __half2 z = __floats2half2_rn(0.f, 0.f);
                *(__half2*)(Yhb + (size_t)r0 * PHS + col)       = z;
                *(__half2*)(Yhb + (size_t)(r0 + 8) * PHS + col) = z;
            }
        }
    }
    if (SUMOUT) {
        __shared__ float rbuf[16];
#pragma unroll
        for (int off = 16; off; off >>= 1) {
            ssum += __shfl_xor_sync(0xffffffffu, ssum, off);
            ssq  += __shfl_xor_sync(0xffffffffu, ssq,  off);
        }
        if (lane == 0) { rbuf[warp] = ssum; rbuf[8 + warp] = ssq; }
        __syncthreads();
        if (tid == 0) {
            float S = 0.f, S2 = 0.f;
#pragma unroll
            for (int w = 0; w < 8; w++) { S += rbuf[w]; S2 += rbuf[8 + w]; }
            atomicAdd(acc + 2 * b, S);
            atomicAdd(acc + 2 * b + 1, S2);
        }
    }
}

// ===== fused flash attention: C[b] = softmax(P P^T / sqrt(200)) @ P  (no A materialization) =====
#define FA_KS_F4 27
#define FA_PS_F4 17
#define FA_KBYTES (128 * FA_KS_F4 * 16)      /* 55296 */
#define FA_PBYTES (200 * FA_PS_F4 * 16)      /* 54400 */
#define FA_BUF (FA_KBYTES + FA_PBYTES)       /* 109696 */
#define FA_SMEM (2 * FA_BUF)                 /* 219392 */

__global__ void __launch_bounds__(256, 1) fattn_kernel(const half* __restrict__ Ph,
                                                       const half* __restrict__ PTh,
                                                       float* __restrict__ C) {
    char* smem = dyn_smem;
    const uint32_t sb = smem_u32(smem);
    const int b = blockIdx.y, s0 = blockIdx.x * 128;
    const int tid = threadIdx.x, warp = tid >> 5, lane = tid & 31;
    const int gid = lane >> 2, tig = lane & 3;
    const int m0 = warp * 16;

    const char* PhB = (const char*)(Ph + (size_t)b * SEQ * PHS);   // row = 416 B
    const char* PTB = (const char*)(PTh + (size_t)b * NPAD * SEQ); // row = 2048 B

    auto stage = [&](int ch, int buf) {
        uint32_t kbase = sb + buf * FA_BUF;
        uint32_t pbase = kbase + FA_KBYTES;
        const char* ksrc = PhB + (size_t)(ch * 128) * 416;
        for (int i = tid; i < 128 * 26; i += 256) {
            int r = i / 26, c4 = i - r * 26;
            cp16(kbase + (r * FA_KS_F4 + c4) * 16, ksrc + (size_t)r * 416 + c4 * 16);
        }
        const char* psrc = PTB + ch * 256;
        for (int i = tid; i < 200 * 16; i += 256) {
            int r = i >> 4, c4 = i & 15;
            cp16(pbase + (r * FA_PS_F4 + c4) * 16, psrc + (size_t)r * 2048 + c4 * 16);
        }
    };

    // persistent Q fragments (13 k-steps of 16 halves)
    uint32_t qf[13][4];
    {
        const uint32_t* q0 = (const uint32_t*)(PhB + (size_t)(s0 + m0 + gid) * 416);
        const uint32_t* q8 = (const uint32_t*)(PhB + (size_t)(s0 + m0 + gid + 8) * 416);
#pragma unroll
        for (int ks = 0; ks < 13; ks++) {
            qf[ks][0] = q0[ks * 8 + tig];
            qf[ks][1] = q8[ks * 8 + tig];
            qf[ks][2] = q0[ks * 8 + tig + 4];
            qf[ks][3] = q8[ks * 8 + tig + 4];
        }
    }

    float o[25][4];
#pragma unroll
    for (int nt = 0; nt < 25; nt++)
#pragma unroll
        for (int q = 0; q < 4; q++) o[nt][q] = 0.f;
    float z0 = 0.f, z8 = 0.f;

    stage(0, 0);
    CP_COMMIT();

    for (int ch = 0; ch < 8; ch++) {
        const int buf = ch & 1;
        CP_WAIT0();
        __syncthreads();
        if (ch < 7) { stage(ch + 1, buf ^ 1); CP_COMMIT(); }

        const uint32_t* Kh  = (const uint32_t*)(smem + buf * FA_BUF);
        const uint32_t* Psh = (const uint32_t*)(smem + buf * FA_BUF + FA_KBYTES);

        uint32_t afr[8][4];
        const float inv = 0.07071067811865475f;
#pragma unroll
        for (int kt = 0; kt < 8; kt++) {
            float sa[4] = {0.f, 0.f, 0.f, 0.f};
            float sc[4] = {0.f, 0.f, 0.f, 0.f};
            const uint32_t* k0p = Kh + (kt * 16 + gid) * 108 + tig;
            const uint32_t* k1p = k0p + 8 * 108;
#pragma unroll
            for (int ks = 0; ks < 13; ks++) {
                uint32_t b0[2] = { k0p[ks * 8], k0p[ks * 8 + 4] };
                mma_f16(sa, qf[ks], b0);
                uint32_t b1[2] = { k1p[ks * 8], k1p[ks * 8 + 4] };
                mma_f16(sc, qf[ks], b1);
            }
            float e0 = __expf(fmaf(sa[0], inv, -8.f));
            float e1 = __expf(fmaf(sa[1], inv, -8.f));
            float e2 = __expf(fmaf(sa[2], inv, -8.f));
            float e3 = __expf(fmaf(sa[3], inv, -8.f));
            float f0 = __expf(fmaf(sc[0], inv, -8.f));
            float f1 = __expf(fmaf(sc[1], inv, -8.f));
            float f2 = __expf(fmaf(sc[2], inv, -8.f));
            float f3 = __expf(fmaf(sc[3], inv, -8.f));
            z0 += (e0 + e1) + (f0 + f1);
            z8 += (e2 + e3) + (f2 + f3);
            afr[kt][0] = pack_h2(e0, e1);
            afr[kt][1] = pack_h2(e2, e3);
            afr[kt][2] = pack_h2(f0, f1);
            afr[kt][3] = pack_h2(f2, f3);
        }
#pragma unroll
        for (int nt = 0; nt < 25; nt++) {
            const uint32_t* bp = Psh + (nt * 8 + gid) * 68 + tig;
#pragma unroll
            for (int kt = 0; kt < 8; kt++) {
                uint32_t bf[2] = { bp[kt * 8], bp[kt * 8 + 4] };
                mma_f16(o[nt], afr[kt], bf);
            }
        }
    }

    // row-sum reduce across tig lanes; normalize; store
    z0 += __shfl_xor_sync(0xffffffffu, z0, 1);
    z0 += __shfl_xor_sync(0xffffffffu, z0, 2);
    z8 += __shfl_xor_sync(0xffffffffu, z8, 1);
    z8 += __shfl_xor_sync(0xffffffffu, z8, 2);
    float rz0 = 1.f / z0, rz8 = 1.f / z8;

    float* Cb  = C + ((size_t)b * SEQ + s0 + m0 + gid) * DIM;
    float* Cb8 = Cb + 8 * DIM;
#pragma unroll
    for (int nt = 0; nt < 25; nt++) {
        int col = nt * 8 + 2 * tig;
        *(float2*)(Cb  + col) = make_float2(o[nt][0] * rz0, o[nt][1] * rz0);
        *(float2*)(Cb8 + col) = make_float2(o[nt][2] * rz8, o[nt][3] * rz8);
    }
}

// ================= final classifier =================
__global__ void final_kernel(const float* __restrict__ t, const float* __restrict__ stats,
                             const float* __restrict__ Wd, const float* __restrict__ bd,
                             float* __restrict__ out) {
    int b = blockIdx.x;
    int c = threadIdx.x;
    float m = stats[2 * b], rs = stats[2 * b + 1];
    const float* row = t + ((size_t)b * SEQ + (SEQ - 1)) * DIM;
    if (c < NCLS) {
        float acc = bd[c];
        for (int d = 0; d < DIM; d++)
            acc += (row[d] - m) * rs * Wd[d * NCLS + c];
        out[b * NCLS + c] = acc;
    }
}

// ================= host launcher =================
extern "C" void kernel_launch(void* const* d_in, const int* in_sizes, int n_in,
                              void* d_out, int out_size) {
    (void)in_sizes; (void)n_in; (void)out_size;
    const int*   x    = (const int*)  d_in[0];
    const float* emb  = (const float*)d_in[1];
    const float* pos  = (const float*)d_in[2];
    const float* Wp   = (const float*)d_in[3];
    const float* bp   = (const float*)d_in[4];
    const float* Wm   = (const float*)d_in[5];
    const float* bm   = (const float*)d_in[6];
    const float* W1   = (const float*)d_in[7];
    const float* b1   = (const float*)d_in[8];
    const float* W2   = (const float*)d_in[9];
    const float* b2   = (const float*)d_in[10];
    const float* Wd   = (const float*)d_in[11];
    const float* bd   = (const float*)d_in[12];
    float* out = (float*)d_out;

    float *h_, *t_, *c_, *WT_, *st_, *ac_;
    half *Ph_, *PTh_;
    cudaGetSymbolAddress((void**)&h_,   g_h);
    cudaGetSymbolAddress((void**)&t_,   g_t);
    cudaGetSymbolAddress((void**)&c_,   g_c);
    cudaGetSymbolAddress((void**)&Ph_,  g_Ph);
    cudaGetSymbolAddress((void**)&PTh_, g_PTh);
    cudaGetSymbolAddress((void**)&WT_,  g_WT);
    cudaGetSymbolAddress((void**)&st_,  g_stats);
    cudaGetSymbolAddress((void**)&ac_,  g_acc);

    const float* WpT = WT_;
    const float* WeT = WT_ + 1 * NPAD * DIM;
    const float* W1T = WT_ + 2 * NPAD * DIM;
    const float* W2T = WT_ + 3 * NPAD * DIM;
    float* st1 = st_;
    float* st2 = st_ + 2 * BATCH;
    float* ac1 = ac_;
    float* ac2 = ac_ + 2 * BATCH;

    const int SM_LG = (128 + 224) * LG_LD * 4;   // 61952

    // RELU, ADDRES, HOUT, ALN, RESLN, TERMS, SUMOUT
    auto L_proj0 = lgemm_kernel<false, false, true,  false, false, 1, false>;
    auto L_proj1 = lgemm_kernel<false, false, true,  true,  false, 1, false>;
    auto L_wm0   = lgemm_kernel<false, true,  false, false, false, 3, true >;
    auto L_wm1   = lgemm_kernel<false, true,  false, false, true,  3, true >;
    auto L_w1    = lgemm_kernel<true,  false, false, true,  false, 1, false>;
    auto L_w2    = lgemm_kernel<false, true,  false, false, true,  3, true >;
    cudaFuncSetAttribute(L_proj0, cudaFuncAttributeMaxDynamicSharedMemorySize, SM_LG);
    cudaFuncSetAttribute(L_proj1, cudaFuncAttributeMaxDynamicSharedMemorySize, SM_LG);
    cudaFuncSetAttribute(L_wm0,   cudaFuncAttributeMaxDynamicSharedMemorySize, SM_LG);
    cudaFuncSetAttribute(L_wm1,   cudaFuncAttributeMaxDynamicSharedMemorySize, SM_LG);
    cudaFuncSetAttribute(L_w1,    cudaFuncAttributeMaxDynamicSharedMemorySize, SM_LG);
    cudaFuncSetAttribute(L_w2,    cudaFuncAttributeMaxDynamicSharedMemorySize, SM_LG);
    cudaFuncSetAttribute(fattn_kernel, cudaFuncAttributeMaxDynamicSharedMemorySize, FA_SMEM);

    const int LGRID = BATCH * SEQ / 128;             // 512
    const int ELT4  = BATCH * SEQ * DIM / 4;

    wprep_kernel<<<dim3((NPAD * DIM + 255) / 256, 4), 256>>>(Wp, Wm, W1, W2, WT_);
    embed_kernel<<<(ELT4 + 255) / 256, 256>>>(x, (const float4*)emb, (const float4*)pos, (float4*)h_);

    for (int st = 0; st < 2; st++) {
        // p = fp16(lnA?(h) @ Wp + bp) -> Ph
        if (st == 0)
            L_proj0<<<LGRID, 256, SM_LG>>>(h_, WpT, bp, nullptr, nullptr, nullptr, nullptr, Ph_, nullptr);
        else
            L_proj1<<<LGRID, 256, SM_LG>>>(h_, WpT, bp, nullptr, st2, nullptr, nullptr, Ph_, nullptr);
        // PTh[b][d][t]
        transpose_h_kernel<<<dim3(SEQ / 32, 7, BATCH), dim3(32, 8)>>>(Ph_, PTh_);
        // fused attention: c = softmax(P P^T / sqrt(200)) @ P
        fattn_kernel<<<dim3(SEQ / 128, BATCH), 256, FA_SMEM>>>(Ph_, PTh_, c_);
        // t = c @ WmEff + bm + lnR?(h)   (3xTF32, ln-sums fused)
        if (st == 0)
            L_wm0<<<LGRID, 256, SM_LG>>>(c_, WeT, bm, h_, nullptr, nullptr, t_, nullptr, ac1);
        else
            L_wm1<<<LGRID, 256, SM_LG>>>(c_, WeT, bm, h_, nullptr, st2, t_, nullptr, ac1);
        finalize_kernel<<<1, 64>>>(ac1, st1);
        // ff1 = relu(ln(t) @ W1 + b1)
        L_w1<<<LGRID, 256, SM_LG>>>(t_, W1T, b1, nullptr, st1, nullptr, c_, nullptr, nullptr);
        // t2 = ff1 @ W2 + b2 + ln(t)   (3xTF32, ln-sums fused) -> h_
        L_w2<<<LGRID, 256, SM_LG>>>(c_, W2T, b2, t_, nullptr, st1, h_, nullptr, ac2);
        finalize_kernel<<<1, 64>>>(ac2, st2);
    }
    final_kernel<<<BATCH, 32>>>(h_, st2, Wd, bd, out);
}

// round 10
// speedup vs baseline: 3.4721x; 1.0058x over previous
#include <cuda_runtime.h>
#include <cuda_fp16.h>
#include <cuda_bf16.h>
#include <math.h>
#include <stdint.h>

#define BATCH 64
#define SEQ   1024
#define DIM   200
#define NCLS  31
#define NHEAD 8
#define LN_EPS 1e-5f
#define NPAD  224
#define PHS   208          /* Ph row stride in halves (416 B) */

// ---------------- scratch (static device memory; no allocations) ----------------
static __device__ float g_h [BATCH * SEQ * DIM];
static __device__ float g_t [BATCH * SEQ * DIM];
static __device__ float g_c [BATCH * SEQ * DIM];
static __device__ half  g_Ph[(size_t)BATCH * SEQ * PHS];
static __device__ half  g_PTh[(size_t)BATCH * NPAD * SEQ];
static __device__ float g_WT[4 * NPAD * DIM];
static __device__ float g_stats[4 * BATCH];
static __device__ float g_acc[4 * BATCH];     // ln sum/sumsq accumulators (BSS zero; finalize resets)

extern __shared__ char dyn_smem[];

// ================= helpers =================
__device__ __forceinline__ float tf32r(float x) {
    uint32_t r;
    asm("cvt.rna.tf32.f32 %0, %1;" : "=r"(r) : "f"(x));
    return __uint_as_float(r);
}
__device__ __forceinline__ void mma_tf32(float c[4], const uint32_t a[4], const uint32_t b[2]) {
    asm volatile(
        "mma.sync.aligned.m16n8k8.row.col.f32.tf32.tf32.f32 "
        "{%0,%1,%2,%3}, {%4,%5,%6,%7}, {%8,%9}, {%0,%1,%2,%3};"
        : "+f"(c[0]), "+f"(c[1]), "+f"(c[2]), "+f"(c[3])
        : "r"(a[0]), "r"(a[1]), "r"(a[2]), "r"(a[3]), "r"(b[0]), "r"(b[1]));
}
__device__ __forceinline__ void mma_f16(float c[4], const uint32_t a[4], const uint32_t b[2]) {
    asm volatile(
        "mma.sync.aligned.m16n8k16.row.col.f32.f16.f16.f32 "
        "{%0,%1,%2,%3}, {%4,%5,%6,%7}, {%8,%9}, {%0,%1,%2,%3};"
        : "+f"(c[0]), "+f"(c[1]), "+f"(c[2]), "+f"(c[3])
        : "r"(a[0]), "r"(a[1]), "r"(a[2]), "r"(a[3]), "r"(b[0]), "r"(b[1]));
}
__device__ __forceinline__ uint32_t smem_u32(const void* p) {
    uint32_t a;
    asm("{ .reg .u64 t; cvta.to.shared.u64 t, %1; cvt.u32.u64 %0, t; }" : "=r"(a) : "l"(p));
    return a;
}
__device__ __forceinline__ void cp16(uint32_t dst, const void* src) {
    asm volatile("cp.async.cg.shared.global [%0], [%1], 16;" :: "r"(dst), "l"(src));
}
#define CP_COMMIT() asm volatile("cp.async.commit_group;" ::: "memory")
#define CP_WAIT0()  asm volatile("cp.async.wait_group 0;" ::: "memory")
__device__ __forceinline__ uint32_t pack_h2(float a, float b) {
    __half2 h = __floats2half2_rn(a, b);
    return *(uint32_t*)&h;
}

// ================= small kernels =================
__global__ void wprep_kernel(const float* __restrict__ Wp, const float* __restrict__ Wm,
                             const float* __restrict__ W1, const float* __restrict__ W2,
                             float* __restrict__ WT) {
    int i = blockIdx.x * blockDim.x + threadIdx.x;
    if (i >= NPAD * DIM) return;
    int n = i / DIM, k = i % DIM;
    int which = blockIdx.y;
    float v = 0.f;
    if (n < DIM) {
        if (which == 0) v = Wp[k * DIM + n];
        else if (which == 1) {
#pragma unroll
            for (int h = 0; h < NHEAD; h++) v += Wm[(h * DIM + k) * DIM + n];
        } else if (which == 2) v = W1[k * DIM + n];
        else v = W2[k * DIM + n];
    }
    WT[which * NPAD * DIM + i] = v;
}

__global__ void embed_kernel(const int* __restrict__ x, const float4* __restrict__ emb,
                             const float4* __restrict__ pos, float4* __restrict__ h) {
    int g = blockIdx.x * blockDim.x + threadIdx.x;
    const int Q = DIM / 4;
    if (g >= BATCH * SEQ * Q) return;
    int q = g % Q;
    int r = g / Q;
    int s = r % SEQ;
    int tok = x[r];
    float4 e = emb[(size_t)tok * Q + q];
    float4 p = pos[(size_t)s * Q + q];
    h[g] = make_float4(e.x + p.x, e.y + p.y, e.z + p.z, e.w + p.w);
}

// transpose Ph[b][t][208] -> PTh[b][d][t]
__global__ void transpose_h_kernel(const half* __restrict__ Ph, half* __restrict__ PTh) {
    __shared__ half tile[32][33];
    int b = blockIdx.z, t0 = blockIdx.x * 32, d0 = blockIdx.y * 32;
    int tx = threadIdx.x, ty = threadIdx.y;
    const half* src = Ph + ((size_t)b * SEQ + t0) * PHS;
    const half hz = __ushort_as_half((unsigned short)0);
#pragma unroll
    for (int k = 0; k < 4; k++) {
        int r = ty + 8 * k;
        int d = d0 + tx;
        tile[r][tx] = (d < PHS) ? src[r * PHS + d] : hz;
    }
    __syncthreads();
    half* dst = PTh + (size_t)b * NPAD * SEQ;
#pragma unroll
    for (int k = 0; k < 4; k++) {
        int d = d0 + ty + 8 * k;
        dst[(size_t)d * SEQ + t0 + tx] = tile[tx][ty + 8 * k];
    }
}

// finalize ln stats from accumulators; reset accumulators (graph-replay invariant)
__global__ void finalize_kernel(float* __restrict__ acc, float* __restrict__ stats) {
    int b = threadIdx.x;
    if (b < BATCH) {
        float S = acc[2 * b], S2 = acc[2 * b + 1];
        const float n = (float)(SEQ * DIM);
        float mean = S / n;
        float var  = S2 / n - mean * mean;
        stats[2 * b]     = mean;
        stats[2 * b + 1] = rsqrtf(var + LN_EPS);
        acc[2 * b] = 0.f; acc[2 * b + 1] = 0.f;
    }
}

// ============ layer GEMM (tf32 mma): Y = op( lnA(X) @ W + bias [+ lnR(res)] ) ============
#define LG_LD 44

template <bool RELU, bool ADDRES, bool HOUT, bool ALN, bool RESLN, int TERMS, bool SUMOUT>
__global__ void __launch_bounds__(256) lgemm_kernel(
    const float* __restrict__ X,
    const float* __restrict__ WT,
    const float* __restrict__ bias,
    const float* __restrict__ res,
    const float* __restrict__ statsA,
    const float* __restrict__ statsR,
    float* __restrict__ Y,
    half*  __restrict__ Yh,
    float* __restrict__ acc)
{
    float* As = (float*)dyn_smem;                  // [128][44]
    float* Bs = (float*)dyn_smem + 128 * LG_LD;    // [224][44]

    const int row0 = blockIdx.x * 128;
    const int b = blockIdx.x >> 3;
    const float4* X4 = (const float4*)(X + (size_t)row0 * DIM);
    const float4* W4 = (const float4*)WT;
    const int tid = threadIdx.x;
    const int warp = tid >> 5, lane = tid & 31;
    const int gid = lane >> 2, tig = lane & 3;
    const int m0 = (warp & 3) * 32;
    const int n0 = (warp >> 2) * 112;

    float mA = 0.f, rA = 1.f;
    if (ALN) { mA = statsA[2 * b]; rA = statsA[2 * b + 1]; }

    float c[2][14][4];
#pragma unroll
    for (int mt = 0; mt < 2; mt++)
#pragma unroll
        for (int nt = 0; nt < 14; nt++)
#pragma unroll
            for (int q = 0; q < 4; q++) c[mt][nt][q] = 0.f;

#pragma unroll
    for (int ch = 0; ch < 5; ch++) {
        const int k0 = ch * 40;
#pragma unroll
        for (int it = 0; it < 5; it++) {
            int idx = tid + it * 256;
            int row = idx / 10, c4 = idx % 10;
            float4 v = X4[(size_t)row * 50 + (k0 >> 2) + c4];
            if (ALN) {
                v.x = (v.x - mA) * rA; v.y = (v.y - mA) * rA;
                v.z = (v.z - mA) * rA; v.w = (v.w - mA) * rA;
            }
            *(float4*)(As + row * LG_LD + c4 * 4) = v;
        }
        for (int idx = tid; idx < 224 * 10; idx += 256) {
            int row = idx / 10, c4 = idx % 10;
            *(float4*)(Bs + row * LG_LD + c4 * 4) = W4[(size_t)row * 50 + (k0 >> 2) + c4];
        }
        __syncthreads();

#pragma unroll
        for (int ks = 0; ks < 5; ks++) {
            const int k = ks * 8;
            uint32_t ahi[2][4], alo[2][4];
#pragma unroll
            for (int mt = 0; mt < 2; mt++) {
                const float* ar = As + (m0 + mt * 16 + gid) * LG_LD + k + tig;
                float a0 = ar[0], a1 = ar[8 * LG_LD], a2 = ar[4], a3 = ar[8 * LG_LD + 4];
                float h0 = tf32r(a0), h1 = tf32r(a1), h2 = tf32r(a2), h3 = tf32r(a3);
                ahi[mt][0] = __float_as_uint(h0); ahi[mt][1] = __float_as_uint(h1);
                ahi[mt][2] = __float_as_uint(h2); ahi[mt][3] = __float_as_uint(h3);
                if (TERMS == 3) {
                    alo[mt][0] = __float_as_uint(a0 - h0);
                    alo[mt][1] = __float_as_uint(a1 - h1);
                    alo[mt][2] = __float_as_uint(a2 - h2);
                    alo[mt][3] = __float_as_uint(a3 - h3);
                }
            }
#pragma unroll
            for (int nt = 0; nt < 14; nt++) {
                const float* br = Bs + (n0 + nt * 8 + gid) * LG_LD + k + tig;
                float b0 = br[0], b1 = br[4];
                float bh0 = tf32r(b0), bh1 = tf32r(b1);
                uint32_t bhi[2] = { __float_as_uint(bh0), __float_as_uint(bh1) };
                if (TERMS == 3) {
                    uint32_t blo[2] = { __float_as_uint(b0 - bh0), __float_as_uint(b1 - bh1) };
#pragma unroll
                    for (int mt = 0; mt < 2; mt++) {
                        mma_tf32(c[mt][nt], ahi[mt], blo);
                        mma_tf32(c[mt][nt], alo[mt], bhi);
                        mma_tf32(c[mt][nt], ahi[mt], bhi);
                    }
                } else {
#pragma unroll
                    for (int mt = 0; mt < 2; mt++) mma_tf32(c[mt][nt], ahi[mt], bhi);
                }
            }
        }
        __syncthreads();
    }

    float mR = 0.f, rR = 1.f;
    if (RESLN) { mR = statsR[2 * b]; rR = statsR[2 * b + 1]; }

    float* Yb = (!HOUT) ? (Y + (size_t)row0 * DIM) : (float*)0;
    half*  Yhb = HOUT ? (Yh + (size_t)row0 * PHS) : (half*)0;
    const float* Rb = ADDRES ? (res + (size_t)row0 * DIM) : (const float*)0;

    float ssum = 0.f, ssq = 0.f;
#pragma unroll
    for (int mt = 0; mt < 2; mt++) {
        int r0 = m0 + mt * 16 + gid;
#pragma unroll
        for (int nt = 0; nt < 14; nt++) {
            int col = n0 + nt * 8 + 2 * tig;
            if (col < DIM) {
                float bx = bias[col], by = bias[col + 1];
                float v0 = c[mt][nt][0] + bx, v1 = c[mt][nt][1] + by;
                float v2 = c[mt][nt][2] + bx, v3 = c[mt][nt][3] + by;
                if (ADDRES) {
                    float q0 = Rb[(size_t)r0 * DIM + col],       q1 = Rb[(size_t)r0 * DIM + col + 1];
                    float q2 = Rb[(size_t)(r0 + 8) * DIM + col], q3 = Rb[(size_t)(r0 + 8) * DIM + col + 1];
                    if (RESLN) {
                        q0 = (q0 - mR) * rR; q1 = (q1 - mR) * rR;
                        q2 = (q2 - mR) * rR; q3 = (q3 - mR) * rR;
                    }
                    v0 += q0; v1 += q1; v2 += q2; v3 += q3;
                }
                if (RELU) {
                    v0 = fmaxf(v0, 0.f); v1 = fmaxf(v1, 0.f);
                    v2 = fmaxf(v2, 0.f); v3 = fmaxf(v3, 0.f);
                }
                if (SUMOUT) {
                    ssum += (v0 + v1) + (v2 + v3);
                    ssq  += v0 * v0 + v1 * v1 + v2 * v2 + v3 * v3;
                }
                if (HOUT) {
                    *(__half2*)(Yhb + (size_t)r0 * PHS + col)       = __floats2half2_rn(v0, v1);
                    *(__half2*)(Yhb + (size_t)(r0 + 8) * PHS + col) = __floats2half2_rn(v2, v3);
                } else {
                    *(float2*)(Yb + (size_t)r0 * DIM + col)       = make_float2(v0, v1);
                    *(float2*)(Yb + (size_t)(r0 + 8) * DIM + col) = make_float2(v2, v3);
                }
            } else if (HOUT && col < PHS) {
                __half2 z = __floats2half2_rn(0.f, 0.f);
                *(__half2*)(Yhb + (size_t)r0 * PHS + col)       = z;
                *(__half2*)(Yhb + (size_t)(r0 + 8) * PHS + col) = z;
            }
        }
    }
    if (SUMOUT) {
        __shared__ float rbuf[16];
#pragma unroll
        for (int off = 16; off; off >>= 1) {
            ssum += __shfl_xor_sync(0xffffffffu, ssum, off);
            ssq  += __shfl_xor_sync(0xffffffffu, ssq,  off);
        }
        if (lane == 0) { rbuf[warp] = ssum; rbuf[8 + warp] = ssq; }
        __syncthreads();
        if (tid == 0) {
            float S = 0.f, S2 = 0.f;
#pragma unroll
            for (int w = 0; w < 8; w++) { S += rbuf[w]; S2 += rbuf[8 + w]; }
            atomicAdd(acc + 2 * b, S);
            atomicAdd(acc + 2 * b + 1, S2);
        }
    }
}

// ===== fused flash attention: C[b] = softmax(P P^T / sqrt(200)) @ P  (no A materialization) =====
#define FA_KS_F4 27
#define FA_PS_F4 17
#define FA_KBYTES (128 * FA_KS_F4 * 16)      /* 55296 */
#define FA_PBYTES (200 * FA_PS_F4 * 16)      /* 54400 */
#define FA_BUF (FA_KBYTES + FA_PBYTES)       /* 109696 */
#define FA_SMEM (2 * FA_BUF)                 /* 219392 */

__global__ void __launch_bounds__(256, 1) fattn_kernel(const half* __restrict__ Ph,
                                                       const half* __restrict__ PTh,
                                                       float* __restrict__ C) {
    char* smem = dyn_smem;
    const uint32_t sb = smem_u32(smem);
    const int b = blockIdx.y, s0 = blockIdx.x * 128;
    const int tid = threadIdx.x, warp = tid >> 5, lane = tid & 31;
    const int gid = lane >> 2, tig = lane & 3;
    const int m0 = warp * 16;

    const char* PhB = (const char*)(Ph + (size_t)b * SEQ * PHS);   // row = 416 B
    const char* PTB = (const char*)(PTh + (size_t)b * NPAD * SEQ); // row = 2048 B

    auto stage = [&](int ch, int buf) {
        uint32_t kbase = sb + buf * FA_BUF;
        uint32_t pbase = kbase + FA_KBYTES;
        const char* ksrc = PhB + (size_t)(ch * 128) * 416;
        for (int i = tid; i < 128 * 26; i += 256) {
            int r = i / 26, c4 = i - r * 26;
            cp16(kbase + (r * FA_KS_F4 + c4) * 16, ksrc + (size_t)r * 416 + c4 * 16);
        }
        const char* psrc = PTB + ch * 256;
        for (int i = tid; i < 200 * 16; i += 256) {
            int r = i >> 4, c4 = i & 15;
            cp16(pbase + (r * FA_PS_F4 + c4) * 16, psrc + (size_t)r * 2048 + c4 * 16);
        }
    };

    // persistent Q fragments (13 k-steps of 16 halves)
    uint32_t qf[13][4];
    {
        const uint32_t* q0 = (const uint32_t*)(PhB + (size_t)(s0 + m0 + gid) * 416);
        const uint32_t* q8 = (const uint32_t*)(PhB + (size_t)(s0 + m0 + gid + 8) * 416);
#pragma unroll
        for (int ks = 0; ks < 13; ks++) {
            qf[ks][0] = q0[ks * 8 + tig];
            qf[ks][1] = q8[ks * 8 + tig];
            qf[ks][2] = q0[ks * 8 + tig + 4];
            qf[ks][3] = q8[ks * 8 + tig + 4];
        }
    }

    float o[25][4];
#pragma unroll
    for (int nt = 0; nt < 25; nt++)
#pragma unroll
        for (int q = 0; q < 4; q++) o[nt][q] = 0.f;
    float z0 = 0.f, z8 = 0.f;

    stage(0, 0);
    CP_COMMIT();

    for (int ch = 0; ch < 8; ch++) {
        const int buf = ch & 1;
        CP_WAIT0();
        __syncthreads();
        if (ch < 7) { stage(ch + 1, buf ^ 1); CP_COMMIT(); }

        const uint32_t* Kh  = (const uint32_t*)(smem + buf * FA_BUF);
        const uint32_t* Psh = (const uint32_t*)(smem + buf * FA_BUF + FA_KBYTES);

        uint32_t afr[8][4];
        const float inv = 0.07071067811865475f;
#pragma unroll
        for (int kt = 0; kt < 8; kt++) {
            float sa[4] = {0.f, 0.f, 0.f, 0.f};
            float sc[4] = {0.f, 0.f, 0.f, 0.f};
            const uint32_t* k0p = Kh + (kt * 16 + gid) * 108 + tig;
            const uint32_t* k1p = k0p + 8 * 108;
#pragma unroll
            for (int ks = 0; ks < 13; ks++) {
                uint32_t b0[2] = { k0p[ks * 8], k0p[ks * 8 + 4] };
                mma_f16(sa, qf[ks], b0);
                uint32_t b1[2] = { k1p[ks * 8], k1p[ks * 8 + 4] };
                mma_f16(sc, qf[ks], b1);
            }
            float e0 = __expf(fmaf(sa[0], inv, -8.f));
            float e1 = __expf(fmaf(sa[1], inv, -8.f));
            float e2 = __expf(fmaf(sa[2], inv, -8.f));
            float e3 = __expf(fmaf(sa[3], inv, -8.f));
            float f0 = __expf(fmaf(sc[0], inv, -8.f));
            float f1 = __expf(fmaf(sc[1], inv, -8.f));
            float f2 = __expf(fmaf(sc[2], inv, -8.f));
            float f3 = __expf(fmaf(sc[3], inv, -8.f));
            z0 += (e0 + e1) + (f0 + f1);
            z8 += (e2 + e3) + (f2 + f3);
            afr[kt][0] = pack_h2(e0, e1);
            afr[kt][1] = pack_h2(e2, e3);
            afr[kt][2] = pack_h2(f0, f1);
            afr[kt][3] = pack_h2(f2, f3);
        }
#pragma unroll
        for (int nt = 0; nt < 25; nt++) {
            const uint32_t* bp = Psh + (nt * 8 + gid) * 68 + tig;
#pragma unroll
            for (int kt = 0; kt < 8; kt++) {
                uint32_t bf[2] = { bp[kt * 8], bp[kt * 8 + 4] };
                mma_f16(o[nt], afr[kt], bf);
            }
        }
    }

    // row-sum reduce across tig lanes; normalize; store
    z0 += __shfl_xor_sync(0xffffffffu, z0, 1);
    z0 += __shfl_xor_sync(0xffffffffu, z0, 2);
    z8 += __shfl_xor_sync(0xffffffffu, z8, 1);
    z8 += __shfl_xor_sync(0xffffffffu, z8, 2);
    float rz0 = 1.f / z0, rz8 = 1.f / z8;

    float* Cb  = C + ((size_t)b * SEQ + s0 + m0 + gid) * DIM;
    float* Cb8 = Cb + 8 * DIM;
#pragma unroll
    for (int nt = 0; nt < 25; nt++) {
        int col = nt * 8 + 2 * tig;
        *(float2*)(Cb  + col) = make_float2(o[nt][0] * rz0, o[nt][1] * rz0);
        *(float2*)(Cb8 + col) = make_float2(o[nt][2] * rz8, o[nt][3] * rz8);
    }
}

// ================= final classifier =================
__global__ void final_kernel(const float* __restrict__ t, const float* __restrict__ stats,
                             const float* __restrict__ Wd, const float* __restrict__ bd,
                             float* __restrict__ out) {
    int b = blockIdx.x;
    int c = threadIdx.x;
    float m = stats[2 * b], rs = stats[2 * b + 1];
    const float* row = t + ((size_t)b * SEQ + (SEQ - 1)) * DIM;
    if (c < NCLS) {
        float acc = bd[c];
        for (int d = 0; d < DIM; d++)
            acc += (row[d] - m) * rs * Wd[d * NCLS + c];
        out[b * NCLS + c] = acc;
    }
}

// ================= host launcher =================
extern "C" void kernel_launch(void* const* d_in, const int* in_sizes, int n_in,
                              void* d_out, int out_size) {
    (void)in_sizes; (void)n_in; (void)out_size;
    const int*   x    = (const int*)  d_in[0];
    const float* emb  = (const float*)d_in[1];
    const float* pos  = (const float*)d_in[2];
    const float* Wp   = (const float*)d_in[3];
    const float* bp   = (const float*)d_in[4];
    const float* Wm   = (const float*)d_in[5];
    const float* bm   = (const float*)d_in[6];
    const float* W1   = (const float*)d_in[7];
    const float* b1   = (const float*)d_in[8];
    const float* W2   = (const float*)d_in[9];
    const float* b2   = (const float*)d_in[10];
    const float* Wd   = (const float*)d_in[11];
    const float* bd   = (const float*)d_in[12];
    float* out = (float*)d_out;

    float *h_, *t_, *c_, *WT_, *st_, *ac_;
    half *Ph_, *PTh_;
    cudaGetSymbolAddress((void**)&h_,   g_h);
    cudaGetSymbolAddress((void**)&t_,   g_t);
    cudaGetSymbolAddress((void**)&c_,   g_c);
    cudaGetSymbolAddress((void**)&Ph_,  g_Ph);
    cudaGetSymbolAddress((void**)&PTh_, g_PTh);
    cudaGetSymbolAddress((void**)&WT_,  g_WT);
    cudaGetSymbolAddress((void**)&st_,  g_stats);
    cudaGetSymbolAddress((void**)&ac_,  g_acc);

    const float* WpT = WT_;
    const float* WeT = WT_ + 1 * NPAD * DIM;
    const float* W1T = WT_ + 2 * NPAD * DIM;
    const float* W2T = WT_ + 3 * NPAD * DIM;
    float* st1 = st_;
    float* st2 = st_ + 2 * BATCH;
    float* ac1 = ac_;
    float* ac2 = ac_ + 2 * BATCH;

    const int SM_LG = (128 + 224) * LG_LD * 4;   // 61952

    // RELU, ADDRES, HOUT, ALN, RESLN, TERMS, SUMOUT
    auto L_proj0 = lgemm_kernel<false, false, true,  false, false, 1, false>;
    auto L_proj1 = lgemm_kernel<false, false, true,  true,  false, 1, false>;
    auto L_wm0   = lgemm_kernel<false, true,  false, false, false, 3, true >;
    auto L_wm1   = lgemm_kernel<false, true,  false, false, true,  3, true >;
    auto L_w1    = lgemm_kernel<true,  false, false, true,  false, 1, false>;
    auto L_w2    = lgemm_kernel<false, true,  false, false, true,  3, true >;
    cudaFuncSetAttribute(L_proj0, cudaFuncAttributeMaxDynamicSharedMemorySize, SM_LG);
    cudaFuncSetAttribute(L_proj1, cudaFuncAttributeMaxDynamicSharedMemorySize, SM_LG);
    cudaFuncSetAttribute(L_wm0,   cudaFuncAttributeMaxDynamicSharedMemorySize, SM_LG);
    cudaFuncSetAttribute(L_wm1,   cudaFuncAttributeMaxDynamicSharedMemorySize, SM_LG);
    cudaFuncSetAttribute(L_w1,    cudaFuncAttributeMaxDynamicSharedMemorySize, SM_LG);
    cudaFuncSetAttribute(L_w2,    cudaFuncAttributeMaxDynamicSharedMemorySize, SM_LG);
    cudaFuncSetAttribute(fattn_kernel, cudaFuncAttributeMaxDynamicSharedMemorySize, FA_SMEM);

    const int LGRID = BATCH * SEQ / 128;             // 512
    const int ELT4  = BATCH * SEQ * DIM / 4;

    wprep_kernel<<<dim3((NPAD * DIM + 255) / 256, 4), 256>>>(Wp, Wm, W1, W2, WT_);
    embed_kernel<<<(ELT4 + 255) / 256, 256>>>(x, (const float4*)emb, (const float4*)pos, (float4*)h_);

    for (int st = 0; st < 2; st++) {
        // p = fp16(lnA?(h) @ Wp + bp) -> Ph
        if (st == 0)
            L_proj0<<<LGRID, 256, SM_LG>>>(h_, WpT, bp, nullptr, nullptr, nullptr, nullptr, Ph_, nullptr);
        else
            L_proj1<<<LGRID, 256, SM_LG>>>(h_, WpT, bp, nullptr, st2, nullptr, nullptr, Ph_, nullptr);
        // PTh[b][d][t]
        transpose_h_kernel<<<dim3(SEQ / 32, 7, BATCH), dim3(32, 8)>>>(Ph_, PTh_);
        // fused attention: c = softmax(P P^T / sqrt(200)) @ P
        fattn_kernel<<<dim3(SEQ / 128, BATCH), 256, FA_SMEM>>>(Ph_, PTh_, c_);
        // t = c @ WmEff + bm + lnR?(h)   (3xTF32, ln-sums fused)
        if (st == 0)
            L_wm0<<<LGRID, 256, SM_LG>>>(c_, WeT, bm, h_, nullptr, nullptr, t_, nullptr, ac1);
        else
            L_wm1<<<LGRID, 256, SM_LG>>>(c_, WeT, bm, h_, nullptr, st2, t_, nullptr, ac1);
        finalize_kernel<<<1, 64>>>(ac1, st1);
        // ff1 = relu(ln(t) @ W1 + b1)
        L_w1<<<LGRID, 256, SM_LG>>>(t_, W1T, b1, nullptr, st1, nullptr, c_, nullptr, nullptr);
        // t2 = ff1 @ W2 + b2 + ln(t)   (3xTF32, ln-sums fused) -> h_
        L_w2<<<LGRID, 256, SM_LG>>>(c_, W2T, b2, t_, nullptr, st1, h_, nullptr, ac2);
        finalize_kernel<<<1, 64>>>(ac2, st2);
    }
    final_kernel<<<BATCH, 32>>>(h_, st2, Wd, bd, out);
}

// round 12
// speedup vs baseline: 4.3202x; 1.2443x over previous
#include <cuda_runtime.h>
#include <cuda_fp16.h>
#include <cuda_bf16.h>
#include <math.h>
#include <stdint.h>

#define BATCH 64
#define SEQ   1024
#define DIM   200
#define NCLS  31
#define NHEAD 8
#define LN_EPS 1e-5f
#define NPAD  224
#define PHS   208          /* Ph row stride in halves (416 B) */
#define KH    208          /* padded K (halves) for layer GEMMs */

// ---------------- scratch (static device memory; no allocations) ----------------
static __device__ float g_h [BATCH * SEQ * DIM];
static __device__ float g_t [BATCH * SEQ * DIM];
static __device__ float g_c [BATCH * SEQ * DIM];
static __device__ half  g_Ph[(size_t)BATCH * SEQ * PHS];
static __device__ half  g_Whi[4 * NPAD * KH];
static __device__ half  g_Wlo[4 * NPAD * KH];
static __device__ float g_stats[4 * BATCH];
static __device__ float g_acc[4 * BATCH];     // ln accumulators (BSS zero; finalize resets)

extern __shared__ char dyn_smem[];

// ================= helpers =================
__device__ __forceinline__ void mma_f16(float c[4], const uint32_t a[4], const uint32_t b[2]) {
    asm volatile(
        "mma.sync.aligned.m16n8k16.row.col.f32.f16.f16.f32 "
        "{%0,%1,%2,%3}, {%4,%5,%6,%7}, {%8,%9}, {%0,%1,%2,%3};"
        : "+f"(c[0]), "+f"(c[1]), "+f"(c[2]), "+f"(c[3])
        : "r"(a[0]), "r"(a[1]), "r"(a[2]), "r"(a[3]), "r"(b[0]), "r"(b[1]));
}
__device__ __forceinline__ uint32_t smem_u32(const void* p) {
    uint32_t a;
    asm("{ .reg .u64 t; cvta.to.shared.u64 t, %1; cvt.u32.u64 %0, t; }" : "=r"(a) : "l"(p));
    return a;
}
__device__ __forceinline__ void cp16(uint32_t dst, const void* src) {
    asm volatile("cp.async.cg.shared.global [%0], [%1], 16;" :: "r"(dst), "l"(src));
}
#define CP_COMMIT() asm volatile("cp.async.commit_group;" ::: "memory")
#define CP_WAIT0()  asm volatile("cp.async.wait_group 0;" ::: "memory")
__device__ __forceinline__ uint32_t pack_h2(float a, float b) {
    __half2 h = __floats2half2_rn(a, b);
    return *(uint32_t*)&h;
}
__device__ __forceinline__ void ldsm_x4_t(uint32_t& r0, uint32_t& r1, uint32_t& r2, uint32_t& r3,
                                          uint32_t addr) {
    asm volatile("ldmatrix.sync.aligned.m8n8.x4.trans.shared.b16 {%0,%1,%2,%3}, [%4];"
                 : "=r"(r0), "=r"(r1), "=r"(r2), "=r"(r3) : "r"(addr));
}

// ================= small kernels =================
// split weights into fp16 hi/lo planes, transposed [n][k], padded to 224x208
__global__ void wprep_kernel(const float* __restrict__ Wp, const float* __restrict__ Wm,
                             const float* __restrict__ W1, const float* __restrict__ W2,
                             half* __restrict__ Whi, half* __restrict__ Wlo) {
    int i = blockIdx.x * blockDim.x + threadIdx.x;
    if (i >= NPAD * KH) return;
    int n = i / KH, k = i % KH;
    int which = blockIdx.y;
    float v = 0.f;
    if (n < DIM && k < DIM) {
        if (which == 0) v = Wp[k * DIM + n];
        else if (which == 1) {
#pragma unroll
            for (int h = 0; h < NHEAD; h++) v += Wm[(h * DIM + k) * DIM + n];
        } else if (which == 2) v = W1[k * DIM + n];
        else v = W2[k * DIM + n];
    }
    half hv = __float2half_rn(v);
    Whi[which * NPAD * KH + i] = hv;
    Wlo[which * NPAD * KH + i] = __float2half_rn(v - __half2float(hv));
}

__global__ void embed_kernel(const int* __restrict__ x, const float4* __restrict__ emb,
                             const float4* __restrict__ pos, float4* __restrict__ h) {
    int g = blockIdx.x * blockDim.x + threadIdx.x;
    const int Q = DIM / 4;
    if (g >= BATCH * SEQ * Q) return;
    int q = g % Q;
    int r = g / Q;
    int s = r % SEQ;
    int tok = x[r];
    float4 e = emb[(size_t)tok * Q + q];
    float4 p = pos[(size_t)s * Q + q];
    h[g] = make_float4(e.x + p.x, e.y + p.y, e.z + p.z, e.w + p.w);
}

// finalize ln stats; reset accumulators (graph-replay invariant)
__global__ void finalize_kernel(float* __restrict__ acc, float* __restrict__ stats) {
    int b = threadIdx.x;
    if (b < BATCH) {
        float S = acc[2 * b], S2 = acc[2 * b + 1];
        const float n = (float)(SEQ * DIM);
        float mean = S / n;
        float var  = S2 / n - mean * mean;
        stats[2 * b]     = mean;
        stats[2 * b + 1] = rsqrtf(var + LN_EPS);
        acc[2 * b] = 0.f; acc[2 * b + 1] = 0.f;
    }
}

// ====== layer GEMM (fp16 hi/lo mma): Y = op( lnA(X) @ W + bias [+ lnR(res)] ) ======
// TERMS=1: 1-term fp16 (~tf32 precision), single K chunk (208).
// TERMS=3: 3-term hi/lo fp16 (~fp32 precision), 2 K chunks (112, 96).
template <bool RELU, bool ADDRES, bool HOUT, bool ALN, bool RESLN, int TERMS, bool SUMOUT>
__global__ void __launch_bounds__(256) lgemm_kernel(
    const float* __restrict__ X,
    const half* __restrict__ Whi,
    const half* __restrict__ Wlo,
    const float* __restrict__ bias,
    const float* __restrict__ res,
    const float* __restrict__ statsA,
    const float* __restrict__ statsR,
    float* __restrict__ Y,
    half*  __restrict__ Yh,
    float* __restrict__ acc)
{
    // byte row stride of smem planes (16B multiple, conflict-free word phase)
    constexpr int BS = (TERMS == 1) ? 432 : 240;
    constexpr int WS = BS / 4;                       // words per row
    constexpr int AHI = 0;
    constexpr int APL = 128 * BS;                    // one A plane bytes
    constexpr int ALO = (TERMS == 3) ? APL : 0;
    constexpr int BHI = (TERMS == 3) ? 2 * APL : APL;
    constexpr int BPL = 224 * BS;
    constexpr int BLO = BHI + BPL;                   // only used when TERMS==3

    char* sm = dyn_smem;
    const int row0 = blockIdx.x * 128;
    const int b = blockIdx.x >> 3;
    const float4* X4 = (const float4*)(X + (size_t)row0 * DIM);
    const float4* Whi4 = (const float4*)Whi;
    const float4* Wlo4 = (const float4*)Wlo;
    const int tid = threadIdx.x;
    const int warp = tid >> 5, lane = tid & 31;
    const int gid = lane >> 2, tig = lane & 3;
    const int m0 = (warp & 3) * 32;
    const int n0 = (warp >> 2) * 112;

    float mA = 0.f, rA = 1.f;
    if (ALN) { mA = statsA[2 * b]; rA = statsA[2 * b + 1]; }

    float c[2][14][4];
#pragma unroll
    for (int mt = 0; mt < 2; mt++)
#pragma unroll
        for (int nt = 0; nt < 14; nt++)
#pragma unroll
            for (int q = 0; q < 4; q++) c[mt][nt][q] = 0.f;

    const int NCH = (TERMS == 1) ? 1 : 2;
#pragma unroll
    for (int ch = 0; ch < NCH; ch++) {
        const int kh0 = (TERMS == 1) ? 0 : ch * 112;           // chunk start (halves)
        const int kc  = (TERMS == 1) ? 208 : (ch == 0 ? 112 : 96);
        const int G   = kc >> 2;                               // A float4 groups
        const int G2  = kc >> 3;                               // B float4 groups (8 halves)

        // stage A (fp32 -> hi/lo halves), optionally layer-normalized
        for (int idx = tid; idx < 128 * G; idx += 256) {
            int row = idx / G, g = idx - row * G;
            int jg = (kh0 >> 2) + g;
            float4 v = (jg < 50) ? X4[(size_t)row * 50 + jg] : make_float4(0.f, 0.f, 0.f, 0.f);
            if (ALN) {
                v.x = (v.x - mA) * rA; v.y = (v.y - mA) * rA;
                v.z = (v.z - mA) * rA; v.w = (v.w - mA) * rA;
            }
            half hx = __float2half_rn(v.x), hy = __float2half_rn(v.y);
            half hz = __float2half_rn(v.z), hw = __float2half_rn(v.w);
            uint2 hi;
            hi.x = ((uint32_t)__half_as_ushort(hx)) | ((uint32_t)__half_as_ushort(hy) << 16);
            hi.y = ((uint32_t)__half_as_ushort(hz)) | ((uint32_t)__half_as_ushort(hw) << 16);
            *(uint2*)(sm + AHI + row * BS + g * 8) = hi;
            if (TERMS == 3) {
                half lx = __float2half_rn(v.x - __half2float(hx));
                half ly = __float2half_rn(v.y - __half2float(hy));
                half lz = __float2half_rn(v.z - __half2float(hz));
                half lw = __float2half_rn(v.w - __half2float(hw));
                uint2 lo;
                lo.x = ((uint32_t)__half_as_ushort(lx)) | ((uint32_t)__half_as_ushort(ly) << 16);
                lo.y = ((uint32_t)__half_as_ushort(lz)) | ((uint32_t)__half_as_ushort(lw) << 16);
                *(uint2*)(sm + ALO + row * BS + g * 8) = lo;
            }
        }
        // stage B (copy fp16 planes)
        for (int idx = tid; idx < 224 * G2; idx += 256) {
            int row = idx / G2, g = idx - row * G2;
            int jg = (kh0 >> 3) + g;
            *(float4*)(sm + BHI + row * BS + g * 16) = Whi4[(size_t)row * 26 + jg];
            if (TERMS == 3)
                *(float4*)(sm + BLO + row * BS + g * 16) = Wlo4[(size_t)row * 26 + jg];
        }
        __syncthreads();

        const uint32_t* Ah = (const uint32_t*)(sm + AHI);
        const uint32_t* Al = (const uint32_t*)(sm + ALO);
        const uint32_t* Bh = (const uint32_t*)(sm + BHI);
        const uint32_t* Bl = (const uint32_t*)(sm + BLO);
        const int nks = kc >> 4;

        for (int ks = 0; ks < nks; ks++) {
            const int kw = ks * 8 + tig;
            uint32_t ahi[2][4], alo[2][4];
#pragma unroll
            for (int mt = 0; mt < 2; mt++) {
                int r = (m0 + mt * 16 + gid) * WS + kw;
                ahi[mt][0] = Ah[r];           ahi[mt][1] = Ah[r + 8 * WS];
                ahi[mt][2] = Ah[r + 4];       ahi[mt][3] = Ah[r + 8 * WS + 4];
                if (TERMS == 3) {
                    alo[mt][0] = Al[r];       alo[mt][1] = Al[r + 8 * WS];
                    alo[mt][2] = Al[r + 4];   alo[mt][3] = Al[r + 8 * WS + 4];
                }
            }
#pragma unroll
            for (int nt = 0; nt < 14; nt++) {
                int r = (n0 + nt * 8 + gid) * WS + kw;
                uint32_t bhi[2] = { Bh[r], Bh[r + 4] };
                if (TERMS == 3) {
                    uint32_t blo[2] = { Bl[r], Bl[r + 4] };
#pragma unroll
                    for (int mt = 0; mt < 2; mt++) {
                        mma_f16(c[mt][nt], ahi[mt], blo);
                        mma_f16(c[mt][nt], alo[mt], bhi);
                        mma_f16(c[mt][nt], ahi[mt], bhi);
                    }
                } else {
#pragma unroll
                    for (int mt = 0; mt < 2; mt++) mma_f16(c[mt][nt], ahi[mt], bhi);
                }
            }
        }
        __syncthreads();
    }

    float mR = 0.f, rR = 1.f;
    if (RESLN) { mR = statsR[2 * b]; rR = statsR[2 * b + 1]; }

    float* Yb = (!HOUT) ? (Y + (size_t)row0 * DIM) : (float*)0;
    half*  Yhb = HOUT ? (Yh + (size_t)row0 * PHS) : (half*)0;
    const float* Rb = ADDRES ? (res + (size_t)row0 * DIM) : (const float*)0;

    float ssum = 0.f, ssq = 0.f;
#pragma unroll
    for (int mt = 0; mt < 2; mt++) {
        int r0 = m0 + mt * 16 + gid;
#pragma unroll
        for (int nt = 0; nt < 14; nt++) {
            int col = n0 + nt * 8 + 2 * tig;
            if (col < DIM) {
                float bx = bias[col], by = bias[col + 1];
                float v0 = c[mt][nt][0] + bx, v1 = c[mt][nt][1] + by;
                float v2 = c[mt][nt][2] + bx, v3 = c[mt][nt][3] + by;
                if (ADDRES) {
                    float q0 = Rb[(size_t)r0 * DIM + col],       q1 = Rb[(size_t)r0 * DIM + col + 1];
                    float q2 = Rb[(size_t)(r0 + 8) * DIM + col], q3 = Rb[(size_t)(r0 + 8) * DIM + col + 1];
                    if (RESLN) {
                        q0 = (q0 - mR) * rR; q1 = (q1 - mR) * rR;
                        q2 = (q2 - mR) * rR; q3 = (q3 - mR) * rR;
                    }
                    v0 += q0; v1 += q1; v2 += q2; v3 += q3;
                }
                if (RELU) {
                    v0 = fmaxf(v0, 0.f); v1 = fmaxf(v1, 0.f);
                    v2 = fmaxf(v2, 0.f); v3 = fmaxf(v3, 0.f);
                }
                if (SUMOUT) {
                    ssum += (v0 + v1) + (v2 + v3);
                    ssq  += v0 * v0 + v1 * v1 + v2 * v2 + v3 * v3;
                }
                if (HOUT) {
                    *(__half2*)(Yhb + (size_t)r0 * PHS + col)       = __floats2half2_rn(v0, v1);
                    *(__half2*)(Yhb + (size_t)(r0 + 8) * PHS + col) = __floats2half2_rn(v2, v3);
                } else {
                    *(float2*)(Yb + (size_t)r0 * DIM + col)       = make_float2(v0, v1);
                    *(float2*)(Yb + (size_t)(r0 + 8) * DIM + col) = make_float2(v2, v3);
                }
            } else if (HOUT && col < PHS) {
                __half2 z = __floats2half2_rn(0.f, 0.f);
                *(__half2*)(Yhb + (size_t)r0 * PHS + col)       = z;
                *(__half2*)(Yhb + (size_t)(r0 + 8) * PHS + col) = z;
            }
        }
    }
    if (SUMOUT) {
        __shared__ float rbuf[16];
#pragma unroll
        for (int off = 16; off; off >>= 1) {
            ssum += __shfl_xor_sync(0xffffffffu, ssum, off);
            ssq  += __shfl_xor_sync(0xffffffffu, ssq,  off);
        }
        if (lane == 0) { rbuf[warp] = ssum; rbuf[8 + warp] = ssq; }
        __syncthreads();
        if (tid == 0) {
            float S = 0.f, S2 = 0.f;
#pragma unroll
            for (int w = 0; w < 8; w++) { S += rbuf[w]; S2 += rbuf[8 + w]; }
            atomicAdd(acc + 2 * b, S);
            atomicAdd(acc + 2 * b + 1, S2);
        }
    }
}

// ===== fused flash attention: single K/V tile (V == K rows), ldmatrix.trans for V frags =====
#define FA_ROWB 432                          /* K-tile row stride bytes (16B-aligned) */
#define FA_BUF  (128 * FA_ROWB)              /* 55296 */
#define FA_SMEM (2 * FA_BUF)                 /* 110592 */

__global__ void __launch_bounds__(256, 1) fattn_kernel(const half* __restrict__ Ph,
                                                       float* __restrict__ C) {
    char* smem = dyn_smem;
    const uint32_t sb = smem_u32(smem);
    const int b = blockIdx.y, s0 = blockIdx.x * 128;
    const int tid = threadIdx.x, warp = tid >> 5, lane = tid & 31;
    const int gid = lane >> 2, tig = lane & 3;
    const int m0 = warp * 16;

    const char* PhB = (const char*)(Ph + (size_t)b * SEQ * PHS);   // row = 416 B

    auto stage = [&](int ch, int buf) {
        uint32_t kbase = sb + buf * FA_BUF;
        const char* ksrc = PhB + (size_t)(ch * 128) * 416;
        for (int i = tid; i < 128 * 26; i += 256) {
            int r = i / 26, c4 = i - r * 26;
            cp16(kbase + r * FA_ROWB + c4 * 16, ksrc + (size_t)r * 416 + c4 * 16);
        }
    };

    // persistent Q fragments (13 k-steps of 16 halves)
    uint32_t qf[13][4];
    {
        const uint32_t* q0 = (const uint32_t*)(PhB + (size_t)(s0 + m0 + gid) * 416);
        const uint32_t* q8 = (const uint32_t*)(PhB + (size_t)(s0 + m0 + gid + 8) * 416);
#pragma unroll
        for (int ks = 0; ks < 13; ks++) {
            qf[ks][0] = q0[ks * 8 + tig];
            qf[ks][1] = q8[ks * 8 + tig];
            qf[ks][2] = q0[ks * 8 + tig + 4];
            qf[ks][3] = q8[ks * 8 + tig + 4];
        }
    }

    // per-lane ldmatrix.x4.trans base: seg0=M1(t+0..7,d0), seg1=M2(t+8..15,d0),
    // seg2=M3(t+0..7,d0+8), seg3=M4(t+8..15,d0+8)
    const uint32_t lbase = (uint32_t)(((lane >> 3) & 1) * 8 * FA_ROWB
                                      + (lane & 7) * FA_ROWB
                                      + ((lane >> 4) & 1) * 16);

    float o[25][4];
#pragma unroll
    for (int nt = 0; nt < 25; nt++)
#pragma unroll
        for (int q = 0; q < 4; q++) o[nt][q] = 0.f;
    float z0 = 0.f, z8 = 0.f;

    stage(0, 0);
    CP_COMMIT();

    for (int ch = 0; ch < 8; ch++) {
        const int buf = ch & 1;
        CP_WAIT0();
        __syncthreads();
        if (ch < 7) { stage(ch + 1, buf ^ 1); CP_COMMIT(); }

        const uint32_t kb = sb + buf * FA_BUF;
        const uint32_t* Kh = (const uint32_t*)(smem + buf * FA_BUF);

        uint32_t afr[8][4];
        const float inv = 0.07071067811865475f;
#pragma unroll
        for (int kt = 0; kt < 8; kt++) {
            float sa[4] = {0.f, 0.f, 0.f, 0.f};
            float sc[4] = {0.f, 0.f, 0.f, 0.f};
            const uint32_t* k0p = Kh + (kt * 16 + gid) * 108 + tig;
            const uint32_t* k1p = k0p + 8 * 108;
#pragma unroll
            for (int ks = 0; ks < 13; ks++) {
                uint32_t b0[2] = { k0p[ks * 8], k0p[ks * 8 + 4] };
                mma_f16(sa, qf[ks], b0);
                uint32_t b1[2] = { k1p[ks * 8], k1p[ks * 8 + 4] };
                mma_f16(sc, qf[ks], b1);
            }
            float e0 = __expf(fmaf(sa[0], inv, -8.f));
            float e1 = __expf(fmaf(sa[1], inv, -8.f));
            float e2 = __expf(fmaf(sa[2], inv, -8.f));
            float e3 = __expf(fmaf(sa[3], inv, -8.f));
            float f0 = __expf(fmaf(sc[0], inv, -8.f));
            float f1 = __expf(fmaf(sc[1], inv, -8.f));
            float f2 = __expf(fmaf(sc[2], inv, -8.f));
            float f3 = __expf(fmaf(sc[3], inv, -8.f));
            z0 += (e0 + e1) + (f0 + f1);
            z8 += (e2 + e3) + (f2 + f3);
            afr[kt][0] = pack_h2(e0, e1);
            afr[kt][1] = pack_h2(e2, e3);
            afr[kt][2] = pack_h2(f0, f1);
            afr[kt][3] = pack_h2(f2, f3);
        }
        // O += probs @ V, V fragments via ldmatrix.trans from the SAME K tile
#pragma unroll
        for (int ntp = 0; ntp < 13; ntp++) {
#pragma unroll
            for (int kt = 0; kt < 8; kt++) {
                uint32_t r0, r1, r2, r3;
                ldsm_x4_t(r0, r1, r2, r3, kb + lbase + kt * (16 * FA_ROWB) + ntp * 32);
                uint32_t bA[2] = { r0, r1 };
                mma_f16(o[2 * ntp], afr[kt], bA);
                if (ntp < 12) {
                    uint32_t bB[2] = { r2, r3 };
                    mma_f16(o[2 * ntp + 1], afr[kt], bB);
                }
            }
        }
    }

    // row-sum reduce across tig lanes; normalize; store
    z0 += __shfl_xor_sync(0xffffffffu, z0, 1);
    z0 += __shfl_xor_sync(0xffffffffu, z0, 2);
    z8 += __shfl_xor_sync(0xffffffffu, z8, 1);
    z8 += __shfl_xor_sync(0xffffffffu, z8, 2);
    float rz0 = 1.f / z0, rz8 = 1.f / z8;

    float* Cb  = C + ((size_t)b * SEQ + s0 + m0 + gid) * DIM;
    float* Cb8 = Cb + 8 * DIM;
#pragma unroll
    for (int nt = 0; nt < 25; nt++) {
        int col = nt * 8 + 2 * tig;
        *(float2*)(Cb  + col) = make_float2(o[nt][0] * rz0, o[nt][1] * rz0);
        *(float2*)(Cb8 + col) = make_float2(o[nt][2] * rz8, o[nt][3] * rz8);
    }
}

// ================= final classifier =================
__global__ void final_kernel(const float* __restrict__ t, const float* __restrict__ stats,
                             const float* __restrict__ Wd, const float* __restrict__ bd,
                             float* __restrict__ out) {
    int b = blockIdx.x;
    int c = threadIdx.x;
    float m = stats[2 * b], rs = stats[2 * b + 1];
    const float* row = t + ((size_t)b * SEQ + (SEQ - 1)) * DIM;
    if (c < NCLS) {
        float acc = bd[c];
        for (int d = 0; d < DIM; d++)
            acc += (row[d] - m) * rs * Wd[d * NCLS + c];
        out[b * NCLS + c] = acc;
    }
}

// ================= host launcher =================
extern "C" void kernel_launch(void* const* d_in, const int* in_sizes, int n_in,
                              void* d_out, int out_size) {
    (void)in_sizes; (void)n_in; (void)out_size;
    const int*   x    = (const int*)  d_in[0];
    const float* emb  = (const float*)d_in[1];
    const float* pos  = (const float*)d_in[2];
    const float* Wp   = (const float*)d_in[3];
    const float* bp   = (const float*)d_in[4];
    const float* Wm   = (const float*)d_in[5];
    const float* bm   = (const float*)d_in[6];
    const float* W1   = (const float*)d_in[7];
    const float* b1   = (const float*)d_in[8];
    const float* W2   = (const float*)d_in[9];
    const float* b2   = (const float*)d_in[10];
    const float* Wd   = (const float*)d_in[11];
    const float* bd   = (const float*)d_in[12];
    float* out = (float*)d_out;

    float *h_, *t_, *c_, *st_, *ac_;
    half *Ph_, *Whi_, *Wlo_;
    cudaGetSymbolAddress((void**)&h_,   g_h);
    cudaGetSymbolAddress((void**)&t_,   g_t);
    cudaGetSymbolAddress((void**)&c_,   g_c);
    cudaGetSymbolAddress((void**)&Ph_,  g_Ph);
    cudaGetSymbolAddress((void**)&Whi_, g_Whi);
    cudaGetSymbolAddress((void**)&Wlo_, g_Wlo);
    cudaGetSymbolAddress((void**)&st_,  g_stats);
    cudaGetSymbolAddress((void**)&ac_,  g_acc);

    const half* WpHi = Whi_;                  const half* WpLo = Wlo_;
    const half* WeHi = Whi_ + 1 * NPAD * KH;  const half* WeLo = Wlo_ + 1 * NPAD * KH;
    const half* W1Hi = Whi_ + 2 * NPAD * KH;  const half* W1Lo = Wlo_ + 2 * NPAD * KH;
    const half* W2Hi = Whi_ + 3 * NPAD * KH;  const half* W2Lo = Wlo_ + 3 * NPAD * KH;
    float* st1 = st_;
    float* st2 = st_ + 2 * BATCH;
    float* ac1 = ac_;
    float* ac2 = ac_ + 2 * BATCH;

    const int SM_LG1 = 128 * 432 + 224 * 432;              // 152064 (TERMS=1)
    const int SM_LG3 = 2 * 128 * 240 + 2 * 224 * 240;      // 168960 (TERMS=3)

    // RELU, ADDRES, HOUT, ALN, RESLN, TERMS, SUMOUT
    auto L_proj0 = lgemm_kernel<false, false, true,  false, false, 1, false>;
    auto L_proj1 = lgemm_kernel<false, false, true,  true,  false, 1, false>;
    auto L_wm0   = lgemm_kernel<false, true,  false, false, false, 3, true >;
    auto L_res3  = lgemm_kernel<false, true,  false, false, true,  3, true >;
    auto L_w1    = lgemm_kernel<true,  false, false, true,  false, 1, false>;
    cudaFuncSetAttribute(L_proj0, cudaFuncAttributeMaxDynamicSharedMemorySize, SM_LG1);
    cudaFuncSetAttribute(L_proj1, cudaFuncAttributeMaxDynamicSharedMemorySize, SM_LG1);
    cudaFuncSetAttribute(L_wm0,   cudaFuncAttributeMaxDynamicSharedMemorySize, SM_LG3);
    cudaFuncSetAttribute(L_res3,  cudaFuncAttributeMaxDynamicSharedMemorySize, SM_LG3);
    cudaFuncSetAttribute(L_w1,    cudaFuncAttributeMaxDynamicSharedMemorySize, SM_LG1);
    cudaFuncSetAttribute(fattn_kernel, cudaFuncAttributeMaxDynamicSharedMemorySize, FA_SMEM);

    const int LGRID = BATCH * SEQ / 128;             // 512
    const int ELT4  = BATCH * SEQ * DIM / 4;

    wprep_kernel<<<dim3((NPAD * KH + 255) / 256, 4), 256>>>(Wp, Wm, W1, W2, Whi_, Wlo_);
    embed_kernel<<<(ELT4 + 255) / 256, 256>>>(x, (const float4*)emb, (const float4*)pos, (float4*)h_);

    for (int st = 0; st < 2; st++) {
        // p = fp16(lnA?(h) @ Wp + bp) -> Ph
        if (st == 0)
            L_proj0<<<LGRID, 256, SM_LG1>>>(h_, WpHi, WpLo, bp, nullptr, nullptr, nullptr, nullptr, Ph_, nullptr);
        else
            L_proj1<<<LGRID, 256, SM_LG1>>>(h_, WpHi, WpLo, bp, nullptr, st2, nullptr, nullptr, Ph_, nullptr);
        // fused attention: c = softmax(P P^T / sqrt(200)) @ P
        fattn_kernel<<<dim3(SEQ / 128, BATCH), 256, FA_SMEM>>>(Ph_, c_);
        // t = c @ WmEff + bm + lnR?(h)   (3-term fp16 trunk, ln-sums fused)
        if (st == 0)
            L_wm0<<<LGRID, 256, SM_LG3>>>(c_, WeHi, WeLo, bm, h_, nullptr, nullptr, t_, nullptr, ac1);
        else
            L_res3<<<LGRID, 256, SM_LG3>>>(c_, WeHi, WeLo, bm, h_, nullptr, st2, t_, nullptr, ac1);
        finalize_kernel<<<1, 64>>>(ac1, st1);
        // ff1 = relu(ln(t) @ W1 + b1)
        L_w1<<<LGRID, 256, SM_LG1>>>(t_, W1Hi, W1Lo, b1, nullptr, st1, nullptr, c_, nullptr, nullptr);
        // t2 = ff1 @ W2 + b2 + ln(t)   (3-term fp16 trunk, ln-sums fused) -> h_
        L_res3<<<LGRID, 256, SM_LG3>>>(c_, W2Hi, W2Lo, b2, t_, nullptr, st1, h_, nullptr, ac2);
        finalize_kernel<<<1, 64>>>(ac2, st2);
    }
    final_kernel<<<BATCH, 32>>>(h_, st2, Wd, bd, out);
}